// round 14
// baseline (speedup 1.0000x reference)
#include <cuda_runtime.h>
#include <cuda_fp16.h>
#include <cstdint>

// ============================================================================
// IDCST2: out = C0 @ x @ S1^T, M=N=4096 fp32.  Plain-sm_103 tensor path
// (mma.sync m16n8k16 f16 + ldmatrix + cp.async).
// R6/R7: two-level fast transform (parity fold + Lee), dense patch rows,
//        fused combines, patch GEMM merged into main launch.
// R9:  single-fp16 operands, 1 MMA per MAC; Lee cap V0=1792 (r<=2.56).
// R10: BK=64, 128B rows (chunk^=row&7 swizzle), A-fragment double buffering.
// R12: non-persistent launch; patch split-K = 4.
// R13: G0..G3 intermediate buffers stored fp16 (consumers re-quantize to f16
//      anyway) -> ~256MB less HBM round-trip across GEMM epilogues + combines.
//      Patch partials stay fp32.
// ============================================================================

#define NDIM 4096
typedef __half f16;

static constexpr int BM = 128;
static constexpr int BN = 128;
static constexpr int BK = 64;
static constexpr int V0 = 1792;           // patch start row
static constexpr int PR = 256;            // patch rows (2048 - V0)
static constexpr int PSPLIT = 4;          // patch split-K chunks

static constexpr int ROWB        = 128;             // 64 f16 = 128B rows
static constexpr int PLANE_BYTES = 128 * ROWB;      // 16384
static constexpr int STAGE_BYTES = 2 * PLANE_BYTES; // 32768 (A, B)
static constexpr int NSTAGE      = 3;
static constexpr int SMEM_BYTES  = NSTAGE * STAGE_BYTES; // 98304

// -------------------- device scratch ----------------------------------------
__device__ float g_table[16384];
__device__ f16 g_op0[(size_t)NDIM * 1024];
__device__ f16 g_op1[(size_t)NDIM * 1024];
__device__ f16 g_op2[(size_t)NDIM * 1024];
__device__ f16 g_op3[(size_t)NDIM * 1024];
__device__ f16 g_big[(size_t)NDIM * 2048];
__device__ float g_b[NDIM];               // boundary vector (stage 1 only)
__device__ f16 g_Se2[1024 * 1024];
__device__ f16 g_So2[1024 * 1024];
__device__ f16 g_Ce2[1024 * 1024];
__device__ f16 g_Co2[1024 * 1024];
__device__ f16 g_SoP[PR * 2048];
__device__ f16 g_CoP[PR * 2048];
// GEMM outputs [1024 x 4096] fp16 (R13)
__device__ f16 g_G0[(size_t)1024 * NDIM];
__device__ f16 g_G1[(size_t)1024 * NDIM];
__device__ f16 g_G2[(size_t)1024 * NDIM];
__device__ f16 g_G3[(size_t)1024 * NDIM];
__device__ float g_patchP[(size_t)PSPLIT * PR * NDIM];

// -------------------- helpers ------------------------------------------------
__device__ __forceinline__ uint32_t smem_to_u32(const void* p) {
    uint32_t a;
    asm("{ .reg .u64 t; cvta.to.shared.u64 t, %1; cvt.u32.u64 %0, t; }" : "=r"(a) : "l"(p));
    return a;
}

__device__ __forceinline__ uint32_t pack_h2(float x, float y) {
    __half2 H = __floats2half2_rn(x, y);
    return *(uint32_t*)&H;
}

// epilogue store: fp32 path (patch) and f16 path (main G buffers)
__device__ __forceinline__ void store2(float* D, size_t idx, float x, float y) {
    *(float2*)(D + idx) = make_float2(x, y);
}
__device__ __forceinline__ void store2(f16* D, size_t idx, float x, float y) {
    *(uint32_t*)(D + idx) = pack_h2(x, y);
}

// unpack 16 consecutive halves starting at p (16B-aligned) into f[0..15]
__device__ __forceinline__ void unpack16(const f16* p, float* f) {
    const __half2* h = (const __half2*)p;
    #pragma unroll
    for (int c = 0; c < 8; ++c) {
        float2 v = __half22float2(h[c]);
        f[2 * c] = v.x;
        f[2 * c + 1] = v.y;
    }
}

// unpack 4 consecutive halves starting at p (8B-aligned) into f[0..3]
__device__ __forceinline__ void unpack4(const f16* p, float* f) {
    const __half2* h = (const __half2*)p;
    float2 v0 = __half22float2(h[0]);
    float2 v1 = __half22float2(h[1]);
    f[0] = v0.x; f[1] = v0.y; f[2] = v1.x; f[3] = v1.y;
}

#define CP_ASYNC16(dst, src) \
    asm volatile("cp.async.cg.shared.global [%0], [%1], 16;" :: "r"(dst), "l"(src))
#define CP_COMMIT() asm volatile("cp.async.commit_group;" ::: "memory")
#define CP_WAIT1()  asm volatile("cp.async.wait_group 1;"  ::: "memory")

#define LDSM4(r, addr) \
    asm volatile("ldmatrix.sync.aligned.m8n8.x4.shared.b16 {%0,%1,%2,%3}, [%4];" \
                 : "=r"((r)[0]), "=r"((r)[1]), "=r"((r)[2]), "=r"((r)[3]) : "r"(addr))

#define MMAF16(d, a, b0, b1) \
    asm volatile("mma.sync.aligned.m16n8k16.row.col.f32.f16.f16.f32 " \
                 "{%0,%1,%2,%3}, {%4,%5,%6,%7}, {%8,%9}, {%0,%1,%2,%3};" \
                 : "+f"((d)[0]), "+f"((d)[1]), "+f"((d)[2]), "+f"((d)[3]) \
                 : "r"((a)[0]), "r"((a)[1]), "r"((a)[2]), "r"((a)[3]), "r"(b0), "r"(b1))

// ---------------------------------------------------------------------------
__global__ void build_table_kernel() {
    int r = blockIdx.x * 256 + threadIdx.x;
    float s, c;
    sincospif((float)r * (1.0f / 8192.0f), &s, &c);
    g_table[r] = s;
}

// inner bases: Se2[i,q]=sin(pi(2i+1)q/2048); So2[i,q]=sin(pi(2i+1)(2q+1)/4096)
__global__ void gen_basis_inner() {
    int t = blockIdx.x * 256 + threadIdx.x;   // 1024*512 threads
    int i = t >> 9;
    int j2 = (t & 511) << 1;
    int step = 4 * (2 * i + 1);
    int a0 = ((2 * i + 1) * 4 * j2) & 16383;
    int a1 = (a0 + step) & 16383;
    int b0 = (2 * (2 * i + 1) * (2 * j2 + 1)) & 16383;
    int b1 = (b0 + step) & 16383;
    size_t off = ((size_t)i << 10) + j2;
    *(uint32_t*)(g_Se2 + off) = pack_h2(g_table[a0], g_table[a1]);
    *(uint32_t*)(g_So2 + off) = pack_h2(g_table[b0], g_table[b1]);
    *(uint32_t*)(g_Ce2 + off) =
        pack_h2(g_table[(a0 + 4096) & 16383], g_table[(a1 + 4096) & 16383]);
    *(uint32_t*)(g_Co2 + off) =
        pack_h2(g_table[(b0 + 4096) & 16383], g_table[(b1 + 4096) & 16383]);
}

// patch bases: SoP[i,q] = sin(pi(2(V0+i)+1)(2q+1)/8192), CoP = cos version
__global__ void gen_basis_patch() {
    int t = blockIdx.x * 256 + threadIdx.x;   // PR*1024 threads
    int i = t >> 10;
    int j2 = (t & 1023) << 1;
    int M = 2 * (V0 + i) + 1;
    int a0 = (M * (2 * j2 + 1)) & 16383;
    int a1 = (a0 + 2 * M) & 16383;
    size_t off = ((size_t)i << 11) + j2;
    *(uint32_t*)(g_SoP + off) = pack_h2(g_table[a0], g_table[a1]);
    *(uint32_t*)(g_CoP + off) =
        pack_h2(g_table[(a0 + 4096) & 16383], g_table[(a1 + 4096) & 16383]);
}

// ---------------------------------------------------------------------------
__global__ void split_x2_kernel(const float* __restrict__ x) {
    int t = blockIdx.x * 256 + threadIdx.x;   // 4096*256 threads
    int p = t >> 8;
    int j = t & 255;
    const float* xr = x + (size_t)p * NDIM + 16 * j;
    float v[16];
    #pragma unroll
    for (int c = 0; c < 4; ++c) {
        float4 f = *(const float4*)(xr + 4 * c);
        v[4 * c] = f.x; v[4 * c + 1] = f.y; v[4 * c + 2] = f.z; v[4 * c + 3] = f.w;
    }
    float xm1 = (j > 0) ? xr[-1] : 0.0f;

    float xo[8], w[8];
    #pragma unroll
    for (int k = 0; k < 8; ++k) xo[k] = v[2 * k + 1];
    w[0] = xo[0] + xm1;
    #pragma unroll
    for (int k = 1; k < 8; ++k) w[k] = xo[k] + xo[k - 1];

    size_t o4 = ((size_t)p << 10) + 4 * j;
    size_t o8 = ((size_t)p << 11) + 8 * j;
    *(uint32_t*)(g_op0 + o4)     = pack_h2(v[0], v[4]);
    *(uint32_t*)(g_op0 + o4 + 2) = pack_h2(v[8], v[12]);
    *(uint32_t*)(g_op1 + o4)     = pack_h2(v[2], v[6]);
    *(uint32_t*)(g_op1 + o4 + 2) = pack_h2(v[10], v[14]);
    *(uint32_t*)(g_op2 + o4)     = pack_h2(w[0], w[2]);
    *(uint32_t*)(g_op2 + o4 + 2) = pack_h2(w[4], w[6]);
    *(uint32_t*)(g_op3 + o4)     = pack_h2(w[1], w[3]);
    *(uint32_t*)(g_op3 + o4 + 2) = pack_h2(w[5], w[7]);
    #pragma unroll
    for (int k = 0; k < 8; k += 2)
        *(uint32_t*)(g_big + o8 + k) = pack_h2(xo[k], xo[k + 1]);
    if (j == 255) g_b[p] = v[15];
}

// ---------------------------------------------------------------------------
// GEMM core: D[m,n] = sum_k A[m,k]*B[n,k]; both operands single fp16.
// BK=64: 4 k16 steps per k-tile, one sync per k-tile, 3-stage cp.async.
// smem: 128B rows, swizzle chunk(16B) ^= row&7.
// A fragments double-buffered across k16 steps; B loaded at step top.
// OutT = f16 (main, packed half2 stores) or float (patch partials).
// ---------------------------------------------------------------------------
template<int KTILES, int LDK, typename OutT>
__device__ __forceinline__ void gemm_core(
    const f16* __restrict__ A, const f16* __restrict__ B,
    OutT* __restrict__ D, int m0, int n0) {
    extern __shared__ char smem[];
    const uint32_t sbase = smem_to_u32(smem);
    const int tid = threadIdx.x;
    const int lane = tid & 31;
    const int wid = tid >> 5;
    const int wm = wid & 3;
    const int wn = wid >> 2;

    const int lr = tid >> 3;       // 0..31
    const int lc = tid & 7;        // 0..7
    const f16* gsrcA = A + (size_t)(m0 + lr) * LDK + lc * 8;
    const f16* gsrcB = B + (size_t)(n0 + lr) * LDK + lc * 8;
    const uint32_t sdst = sbase + lr * ROWB + (uint32_t)((lc ^ (lr & 7)) << 4);

    uint32_t soff[4];
    #pragma unroll
    for (int s = 0; s < 4; ++s)
        soff[s] = (uint32_t)(((((s << 1) + (lane >> 4)) ^ (lane & 7)) << 4));
    const uint32_t a_row = (uint32_t)((wm * 32 + (lane & 15)) * ROWB);
    const uint32_t b_row = (uint32_t)((wn * 64 + (lane & 15)) * ROWB);

    float acc[2][8][4];
    #pragma unroll
    for (int a = 0; a < 2; ++a)
        #pragma unroll
        for (int b = 0; b < 8; ++b)
            #pragma unroll
            for (int c = 0; c < 4; ++c) acc[a][b][c] = 0.0f;

    auto load_stage = [&](int stage, int kt) {
        const f16* sA = gsrcA + kt * BK;
        const f16* sB = gsrcB + kt * BK;
        uint32_t dA = sdst + stage * STAGE_BYTES;
        uint32_t dB = dA + PLANE_BYTES;
        #pragma unroll
        for (int r = 0; r < 4; ++r) {
            CP_ASYNC16(dA + r * (32 * ROWB), sA + (size_t)(32 * r) * LDK);
            CP_ASYNC16(dB + r * (32 * ROWB), sB + (size_t)(32 * r) * LDK);
        }
    };

    load_stage(0, 0);
    CP_COMMIT();
    load_stage(1, 1);
    CP_COMMIT();

    int cs = 0, ls = 2;
    for (int kt = 0; kt < KTILES; ++kt) {
        CP_WAIT1();
        __syncthreads();
        if (kt + 2 < KTILES) load_stage(ls, kt + 2);
        CP_COMMIT();

        const uint32_t stg = sbase + cs * STAGE_BYTES;
        uint32_t af[2][2][4];
        LDSM4(af[0][0], stg + a_row + soff[0]);
        LDSM4(af[0][1], stg + a_row + 2048 + soff[0]);

        #pragma unroll
        for (int s = 0; s < 4; ++s) {
            const int cur = s & 1, nxt = cur ^ 1;
            uint32_t bf[4][4];
            #pragma unroll
            for (int g = 0; g < 4; ++g)
                LDSM4(bf[g], stg + PLANE_BYTES + b_row + g * 2048 + soff[s]);
            if (s < 3) {
                LDSM4(af[nxt][0], stg + a_row + soff[s + 1]);
                LDSM4(af[nxt][1], stg + a_row + 2048 + soff[s + 1]);
            }
            #pragma unroll
            for (int g = 0; g < 4; ++g) {
                MMAF16(acc[0][2 * g],     af[cur][0], bf[g][0], bf[g][2]);
                MMAF16(acc[1][2 * g],     af[cur][1], bf[g][0], bf[g][2]);
                MMAF16(acc[0][2 * g + 1], af[cur][0], bf[g][1], bf[g][3]);
                MMAF16(acc[1][2 * g + 1], af[cur][1], bf[g][1], bf[g][3]);
            }
        }
        cs = (cs == 2) ? 0 : cs + 1;
        ls = (ls == 2) ? 0 : ls + 1;
    }

    const int r0 = m0 + wm * 32 + (lane >> 2);
    const int c0 = n0 + wn * 64 + (lane & 3) * 2;
    #pragma unroll
    for (int mt = 0; mt < 2; ++mt)
        #pragma unroll
        for (int nt = 0; nt < 8; ++nt) {
            int row = r0 + mt * 16;
            int col = c0 + nt * 8;
            store2(D, (size_t)row * NDIM + col, acc[mt][nt][0], acc[mt][nt][1]);
            store2(D, (size_t)(row + 8) * NDIM + col, acc[mt][nt][2], acc[mt][nt][3]);
        }
}

struct FusedArgs {
    const f16 *A[4], *B[4];
    f16* D[4];
    const f16 *PA;            // patch basis [PR x 2048]
};

// Merged launch: bid<1024 -> main tiles; bid>=1024 -> patch split-K tiles.
// Patch: 256 CTAs = 4 z-chunks x 2 m-tiles x 32 n-tiles, each K=512 (8 ktiles).
__global__ void __launch_bounds__(256, 2) gemm_fused_kernel(FusedArgs a) {
    int bid = blockIdx.x;
    if (bid < 1024) {
        int z = bid >> 8;
        gemm_core<16, 1024, f16>(a.A[z], a.B[z], a.D[z],
                                 ((bid >> 5) & 7) * BM, (bid & 31) * BN);
    } else {
        int p = bid - 1024;
        int z = p >> 6;
        int rem = p & 63;
        gemm_core<8, 2048, float>(a.PA + z * 512, g_big + z * 512,
                                  g_patchP + (size_t)z * PR * NDIM,
                                  (rem >> 5) * BM, (rem & 31) * BN);
    }
}

// ---------------------------------------------------------------------------
// outer combine, stage 1 (sin): mirror fold inline, emits stage-2 operands.
// G buffers are fp16 (R13).
// ---------------------------------------------------------------------------
__global__ void outer_combine1_kernel() {
    int t = blockIdx.x * 256 + threadIdx.x;   // 2048*256 threads
    int v = t >> 8;
    int j = t & 255;                          // p block [16j, 16j+16)
    const float sign = 1.0f;
    int vr = (v < 1024) ? v : 2047 - v;
    float a0 = (v < 1024) ? 1.0f : -sign;
    float a1 = (v < 1024) ? 1.0f : sign;
    size_t rowG = ((size_t)vr << 12) + 16 * j;

    float f0v[16], f1v[16], E[16], O[16];
    unpack16(g_G0 + rowG, f0v);
    unpack16(g_G1 + rowG, f1v);
    #pragma unroll
    for (int m = 0; m < 16; ++m) E[m] = a0 * f0v[m] + a1 * f1v[m];
    float En = (j > 0)
        ? (a0 * __half2float(g_G0[rowG - 1]) + a1 * __half2float(g_G1[rowG - 1]))
        : 0.0f;
    float On;
    if (v < V0) {
        float r = 0.5f / cospif((2.0f * v + 1.0f) * (1.0f / 8192.0f));
        float s = (v & 1) ? -1.0f : 1.0f;
        float f2v[16], f3v[16];
        unpack16(g_G2 + rowG, f2v);
        unpack16(g_G3 + rowG, f3v);
        #pragma unroll
        for (int c = 0; c < 4; ++c) {
            float4 b = *(const float4*)(g_b + 16 * j + 4 * c);
            O[4 * c]     = r * (a0 * f2v[4 * c]     + a1 * f3v[4 * c]     + s * b.x);
            O[4 * c + 1] = r * (a0 * f2v[4 * c + 1] + a1 * f3v[4 * c + 1] + s * b.y);
            O[4 * c + 2] = r * (a0 * f2v[4 * c + 2] + a1 * f3v[4 * c + 2] + s * b.z);
            O[4 * c + 3] = r * (a0 * f2v[4 * c + 3] + a1 * f3v[4 * c + 3] + s * b.w);
        }
        On = (j > 0)
           ? r * (a0 * __half2float(g_G2[rowG - 1]) +
                  a1 * __half2float(g_G3[rowG - 1]) + s * g_b[16 * j - 1])
           : 0.0f;
    } else {
        size_t rowP = ((size_t)(v - V0) << 12) + 16 * j;
        #pragma unroll
        for (int m = 0; m < 16; ++m) O[m] = 0.0f;
        On = 0.0f;
        #pragma unroll
        for (int z = 0; z < PSPLIT; ++z) {
            size_t base = (size_t)z * PR * NDIM + rowP;
            #pragma unroll
            for (int c = 0; c < 4; ++c) {
                float4 f = *(const float4*)(g_patchP + base + 4 * c);
                O[4 * c] += f.x; O[4 * c + 1] += f.y;
                O[4 * c + 2] += f.z; O[4 * c + 3] += f.w;
            }
            if (j > 0) On += g_patchP[base - 1];
        }
    }

    #pragma unroll
    for (int half = 0; half < 2; ++half) {
        int row = half ? (4095 - v) : v;
        float yt[16], ytn;
        if (half == 0) {
            #pragma unroll
            for (int m = 0; m < 16; ++m) yt[m] = E[m] + O[m];
            ytn = En + On;
        } else {
            #pragma unroll
            for (int m = 0; m < 16; ++m) yt[m] = O[m] - E[m];
            ytn = On - En;
        }
        float yto[8], wc[8];
        #pragma unroll
        for (int k = 0; k < 8; ++k) yto[k] = yt[2 * k + 1];
        wc[0] = yto[0] + ytn;
        #pragma unroll
        for (int k = 1; k < 8; ++k) wc[k] = yto[k] + yto[k - 1];

        size_t o4 = ((size_t)row << 10) + 4 * j;
        size_t o8 = ((size_t)row << 11) + 8 * j;
        *(uint32_t*)(g_op0 + o4)     = pack_h2(yt[0], yt[4]);
        *(uint32_t*)(g_op0 + o4 + 2) = pack_h2(yt[8], yt[12]);
        *(uint32_t*)(g_op1 + o4)     = pack_h2(yt[2], yt[6]);
        *(uint32_t*)(g_op1 + o4 + 2) = pack_h2(yt[10], yt[14]);
        *(uint32_t*)(g_op2 + o4)     = pack_h2(wc[0], wc[2]);
        *(uint32_t*)(g_op2 + o4 + 2) = pack_h2(wc[4], wc[6]);
        *(uint32_t*)(g_op3 + o4)     = pack_h2(wc[1], wc[3]);
        *(uint32_t*)(g_op3 + o4 + 2) = pack_h2(wc[5], wc[7]);
        #pragma unroll
        for (int k = 0; k < 8; k += 2)
            *(uint32_t*)(g_big + o8 + k) = pack_h2(yto[k], yto[k + 1]);
    }
}

// stage 2 (cos, sign=-1, no boundary): out[u]=E+O; out[4095-u]=E-O
__global__ void outer_combine2_kernel(float* __restrict__ out) {
    int t = blockIdx.x * 256 + threadIdx.x;   // 2048*1024 threads
    int u = t >> 10;
    int j = t & 1023;
    const float sign = -1.0f;
    int ur = (u < 1024) ? u : 2047 - u;
    float a0 = (u < 1024) ? 1.0f : -sign;
    float a1 = (u < 1024) ? 1.0f : sign;
    size_t rowG = ((size_t)ur << 12) + 4 * j;

    float f0v[4], f1v[4];
    unpack4(g_G0 + rowG, f0v);
    unpack4(g_G1 + rowG, f1v);
    float4 e = make_float4(a0 * f0v[0] + a1 * f1v[0], a0 * f0v[1] + a1 * f1v[1],
                           a0 * f0v[2] + a1 * f1v[2], a0 * f0v[3] + a1 * f1v[3]);
    float4 o;
    if (u < V0) {
        float r = 0.5f / cospif((2.0f * u + 1.0f) * (1.0f / 8192.0f));
        float f2v[4], f3v[4];
        unpack4(g_G2 + rowG, f2v);
        unpack4(g_G3 + rowG, f3v);
        o = make_float4(r * (a0 * f2v[0] + a1 * f3v[0]), r * (a0 * f2v[1] + a1 * f3v[1]),
                        r * (a0 * f2v[2] + a1 * f3v[2]), r * (a0 * f2v[3] + a1 * f3v[3]));
    } else {
        size_t rowP = ((size_t)(u - V0) << 12) + 4 * j;
        o = make_float4(0.f, 0.f, 0.f, 0.f);
        #pragma unroll
        for (int z = 0; z < PSPLIT; ++z) {
            float4 f = *(const float4*)(g_patchP + (size_t)z * PR * NDIM + rowP);
            o.x += f.x; o.y += f.y; o.z += f.z; o.w += f.w;
        }
    }
    *(float4*)(out + ((size_t)u << 12) + 4 * j) =
        make_float4(e.x + o.x, e.y + o.y, e.z + o.z, e.w + o.w);
    *(float4*)(out + ((size_t)(4095 - u) << 12) + 4 * j) =
        make_float4(e.x - o.x, e.y - o.y, e.z - o.z, e.w - o.w);
}

// ---------------------------------------------------------------------------
extern "C" void kernel_launch(void* const* d_in, const int* in_sizes, int n_in,
                              void* d_out, int out_size) {
    const float* x = (const float*)d_in[0];
    float* out = (float*)d_out;

    f16 *op0, *op1, *op2, *op3;
    f16 *Se2, *So2, *Ce2, *Co2, *SoP, *CoP;
    f16 *G0, *G1, *G2, *G3;
    cudaGetSymbolAddress((void**)&op0, g_op0);
    cudaGetSymbolAddress((void**)&op1, g_op1);
    cudaGetSymbolAddress((void**)&op2, g_op2);
    cudaGetSymbolAddress((void**)&op3, g_op3);
    cudaGetSymbolAddress((void**)&Se2, g_Se2);
    cudaGetSymbolAddress((void**)&So2, g_So2);
    cudaGetSymbolAddress((void**)&Ce2, g_Ce2);
    cudaGetSymbolAddress((void**)&Co2, g_Co2);
    cudaGetSymbolAddress((void**)&SoP, g_SoP);
    cudaGetSymbolAddress((void**)&CoP, g_CoP);
    cudaGetSymbolAddress((void**)&G0, g_G0); cudaGetSymbolAddress((void**)&G1, g_G1);
    cudaGetSymbolAddress((void**)&G2, g_G2); cudaGetSymbolAddress((void**)&G3, g_G3);

    cudaFuncSetAttribute(gemm_fused_kernel,
                         cudaFuncAttributeMaxDynamicSharedMemorySize, SMEM_BYTES);

    build_table_kernel<<<64, 256>>>();
    gen_basis_inner<<<(1024 * 512) / 256, 256>>>();
    gen_basis_patch<<<(PR * 1024) / 256, 256>>>();
    split_x2_kernel<<<(NDIM * 256) / 256, 256>>>(x);

    // ---- stage 1 (sin along q) ----
    FusedArgs a1;
    a1.A[0] = Se2; a1.B[0] = op0; a1.D[0] = G0;
    a1.A[1] = So2; a1.B[1] = op1; a1.D[1] = G1;
    a1.A[2] = Se2; a1.B[2] = op2; a1.D[2] = G2;
    a1.A[3] = So2; a1.B[3] = op3; a1.D[3] = G3;
    a1.PA = SoP;
    gemm_fused_kernel<<<1024 + 256, 256, SMEM_BYTES>>>(a1);
    outer_combine1_kernel<<<(2048 * 256) / 256, 256>>>();

    // ---- stage 2 (cos along p) ----
    FusedArgs a2;
    a2.A[0] = Ce2; a2.B[0] = op0; a2.D[0] = G0;
    a2.A[1] = Co2; a2.B[1] = op1; a2.D[1] = G1;
    a2.A[2] = Ce2; a2.B[2] = op2; a2.D[2] = G2;
    a2.A[3] = Co2; a2.B[3] = op3; a2.D[3] = G3;
    a2.PA = CoP;
    gemm_fused_kernel<<<1024 + 256, 256, SMEM_BYTES>>>(a2);
    outer_combine2_kernel<<<(2048 * 1024) / 256, 256>>>(out);
}

// round 15
// speedup vs baseline: 1.6606x; 1.6606x over previous
#include <cuda_runtime.h>
#include <cuda_fp16.h>
#include <cstdint>

// ============================================================================
// IDCST2: out = C0 @ x @ S1^T, M=N=4096 fp32.  Plain-sm_103 tensor path
// (mma.sync m16n8k16 f16 + ldmatrix + cp.async).
// R6/R7: two-level fast transform (parity fold + Lee), dense patch rows,
//        fused combines, patch GEMM merged into main launch.
// R9:  single-fp16 operands, 1 MMA per MAC; Lee cap V0=1792 (r<=2.56).
// R10: BK=64, 128B rows (chunk^=row&7 swizzle), A-fragment double buffering.
// R12: non-persistent launch; patch split-K = 4.   [best: 311.4 us]
// R14: revert R13 (fp16 G buffers regressed 311->514: scattered 4B stores +
//      dual-instantiation register pressure). This is the R12 configuration.
// ============================================================================

#define NDIM 4096
typedef __half f16;

static constexpr int BM = 128;
static constexpr int BN = 128;
static constexpr int BK = 64;
static constexpr int V0 = 1792;           // patch start row
static constexpr int PR = 256;            // patch rows (2048 - V0)
static constexpr int PSPLIT = 4;          // patch split-K chunks

static constexpr int ROWB        = 128;             // 64 f16 = 128B rows
static constexpr int PLANE_BYTES = 128 * ROWB;      // 16384
static constexpr int STAGE_BYTES = 2 * PLANE_BYTES; // 32768 (A, B)
static constexpr int NSTAGE      = 3;
static constexpr int SMEM_BYTES  = NSTAGE * STAGE_BYTES; // 98304

// -------------------- device scratch ----------------------------------------
__device__ float g_table[16384];
__device__ f16 g_op0[(size_t)NDIM * 1024];
__device__ f16 g_op1[(size_t)NDIM * 1024];
__device__ f16 g_op2[(size_t)NDIM * 1024];
__device__ f16 g_op3[(size_t)NDIM * 1024];
__device__ f16 g_big[(size_t)NDIM * 2048];
__device__ float g_b[NDIM];               // boundary vector (stage 1 only)
__device__ f16 g_Se2[1024 * 1024];
__device__ f16 g_So2[1024 * 1024];
__device__ f16 g_Ce2[1024 * 1024];
__device__ f16 g_Co2[1024 * 1024];
__device__ f16 g_SoP[PR * 2048];
__device__ f16 g_CoP[PR * 2048];
__device__ float g_G0[(size_t)1024 * NDIM];
__device__ float g_G1[(size_t)1024 * NDIM];
__device__ float g_G2[(size_t)1024 * NDIM];
__device__ float g_G3[(size_t)1024 * NDIM];
__device__ float g_patchP[(size_t)PSPLIT * PR * NDIM];

// -------------------- helpers ------------------------------------------------
__device__ __forceinline__ uint32_t smem_to_u32(const void* p) {
    uint32_t a;
    asm("{ .reg .u64 t; cvta.to.shared.u64 t, %1; cvt.u32.u64 %0, t; }" : "=r"(a) : "l"(p));
    return a;
}

__device__ __forceinline__ uint32_t pack_h2(float x, float y) {
    __half2 H = __floats2half2_rn(x, y);
    return *(uint32_t*)&H;
}

#define CP_ASYNC16(dst, src) \
    asm volatile("cp.async.cg.shared.global [%0], [%1], 16;" :: "r"(dst), "l"(src))
#define CP_COMMIT() asm volatile("cp.async.commit_group;" ::: "memory")
#define CP_WAIT1()  asm volatile("cp.async.wait_group 1;"  ::: "memory")

#define LDSM4(r, addr) \
    asm volatile("ldmatrix.sync.aligned.m8n8.x4.shared.b16 {%0,%1,%2,%3}, [%4];" \
                 : "=r"((r)[0]), "=r"((r)[1]), "=r"((r)[2]), "=r"((r)[3]) : "r"(addr))

#define MMAF16(d, a, b0, b1) \
    asm volatile("mma.sync.aligned.m16n8k16.row.col.f32.f16.f16.f32 " \
                 "{%0,%1,%2,%3}, {%4,%5,%6,%7}, {%8,%9}, {%0,%1,%2,%3};" \
                 : "+f"((d)[0]), "+f"((d)[1]), "+f"((d)[2]), "+f"((d)[3]) \
                 : "r"((a)[0]), "r"((a)[1]), "r"((a)[2]), "r"((a)[3]), "r"(b0), "r"(b1))

// ---------------------------------------------------------------------------
__global__ void build_table_kernel() {
    int r = blockIdx.x * 256 + threadIdx.x;
    float s, c;
    sincospif((float)r * (1.0f / 8192.0f), &s, &c);
    g_table[r] = s;
}

// inner bases: Se2[i,q]=sin(pi(2i+1)q/2048); So2[i,q]=sin(pi(2i+1)(2q+1)/4096)
__global__ void gen_basis_inner() {
    int t = blockIdx.x * 256 + threadIdx.x;   // 1024*512 threads
    int i = t >> 9;
    int j2 = (t & 511) << 1;
    int step = 4 * (2 * i + 1);
    int a0 = ((2 * i + 1) * 4 * j2) & 16383;
    int a1 = (a0 + step) & 16383;
    int b0 = (2 * (2 * i + 1) * (2 * j2 + 1)) & 16383;
    int b1 = (b0 + step) & 16383;
    size_t off = ((size_t)i << 10) + j2;
    *(uint32_t*)(g_Se2 + off) = pack_h2(g_table[a0], g_table[a1]);
    *(uint32_t*)(g_So2 + off) = pack_h2(g_table[b0], g_table[b1]);
    *(uint32_t*)(g_Ce2 + off) =
        pack_h2(g_table[(a0 + 4096) & 16383], g_table[(a1 + 4096) & 16383]);
    *(uint32_t*)(g_Co2 + off) =
        pack_h2(g_table[(b0 + 4096) & 16383], g_table[(b1 + 4096) & 16383]);
}

// patch bases: SoP[i,q] = sin(pi(2(V0+i)+1)(2q+1)/8192), CoP = cos version
__global__ void gen_basis_patch() {
    int t = blockIdx.x * 256 + threadIdx.x;   // PR*1024 threads
    int i = t >> 10;
    int j2 = (t & 1023) << 1;
    int M = 2 * (V0 + i) + 1;
    int a0 = (M * (2 * j2 + 1)) & 16383;
    int a1 = (a0 + 2 * M) & 16383;
    size_t off = ((size_t)i << 11) + j2;
    *(uint32_t*)(g_SoP + off) = pack_h2(g_table[a0], g_table[a1]);
    *(uint32_t*)(g_CoP + off) =
        pack_h2(g_table[(a0 + 4096) & 16383], g_table[(a1 + 4096) & 16383]);
}

// ---------------------------------------------------------------------------
__global__ void split_x2_kernel(const float* __restrict__ x) {
    int t = blockIdx.x * 256 + threadIdx.x;   // 4096*256 threads
    int p = t >> 8;
    int j = t & 255;
    const float* xr = x + (size_t)p * NDIM + 16 * j;
    float v[16];
    #pragma unroll
    for (int c = 0; c < 4; ++c) {
        float4 f = *(const float4*)(xr + 4 * c);
        v[4 * c] = f.x; v[4 * c + 1] = f.y; v[4 * c + 2] = f.z; v[4 * c + 3] = f.w;
    }
    float xm1 = (j > 0) ? xr[-1] : 0.0f;

    float xo[8], w[8];
    #pragma unroll
    for (int k = 0; k < 8; ++k) xo[k] = v[2 * k + 1];
    w[0] = xo[0] + xm1;
    #pragma unroll
    for (int k = 1; k < 8; ++k) w[k] = xo[k] + xo[k - 1];

    size_t o4 = ((size_t)p << 10) + 4 * j;
    size_t o8 = ((size_t)p << 11) + 8 * j;
    *(uint32_t*)(g_op0 + o4)     = pack_h2(v[0], v[4]);
    *(uint32_t*)(g_op0 + o4 + 2) = pack_h2(v[8], v[12]);
    *(uint32_t*)(g_op1 + o4)     = pack_h2(v[2], v[6]);
    *(uint32_t*)(g_op1 + o4 + 2) = pack_h2(v[10], v[14]);
    *(uint32_t*)(g_op2 + o4)     = pack_h2(w[0], w[2]);
    *(uint32_t*)(g_op2 + o4 + 2) = pack_h2(w[4], w[6]);
    *(uint32_t*)(g_op3 + o4)     = pack_h2(w[1], w[3]);
    *(uint32_t*)(g_op3 + o4 + 2) = pack_h2(w[5], w[7]);
    #pragma unroll
    for (int k = 0; k < 8; k += 2)
        *(uint32_t*)(g_big + o8 + k) = pack_h2(xo[k], xo[k + 1]);
    if (j == 255) g_b[p] = v[15];
}

// ---------------------------------------------------------------------------
// GEMM core: D[m,n] = sum_k A[m,k]*B[n,k]; both operands single fp16.
// BK=64: 4 k16 steps per k-tile, one sync per k-tile, 3-stage cp.async.
// smem: 128B rows, swizzle chunk(16B) ^= row&7.
// A fragments double-buffered across k16 steps; B loaded at step top.
// ---------------------------------------------------------------------------
template<int KTILES, int LDK>
__device__ __forceinline__ void gemm_core(
    const f16* __restrict__ A, const f16* __restrict__ B,
    float* __restrict__ D, int m0, int n0) {
    extern __shared__ char smem[];
    const uint32_t sbase = smem_to_u32(smem);
    const int tid = threadIdx.x;
    const int lane = tid & 31;
    const int wid = tid >> 5;
    const int wm = wid & 3;
    const int wn = wid >> 2;

    const int lr = tid >> 3;       // 0..31
    const int lc = tid & 7;        // 0..7
    const f16* gsrcA = A + (size_t)(m0 + lr) * LDK + lc * 8;
    const f16* gsrcB = B + (size_t)(n0 + lr) * LDK + lc * 8;
    const uint32_t sdst = sbase + lr * ROWB + (uint32_t)((lc ^ (lr & 7)) << 4);

    uint32_t soff[4];
    #pragma unroll
    for (int s = 0; s < 4; ++s)
        soff[s] = (uint32_t)(((((s << 1) + (lane >> 4)) ^ (lane & 7)) << 4));
    const uint32_t a_row = (uint32_t)((wm * 32 + (lane & 15)) * ROWB);
    const uint32_t b_row = (uint32_t)((wn * 64 + (lane & 15)) * ROWB);

    float acc[2][8][4];
    #pragma unroll
    for (int a = 0; a < 2; ++a)
        #pragma unroll
        for (int b = 0; b < 8; ++b)
            #pragma unroll
            for (int c = 0; c < 4; ++c) acc[a][b][c] = 0.0f;

    auto load_stage = [&](int stage, int kt) {
        const f16* sA = gsrcA + kt * BK;
        const f16* sB = gsrcB + kt * BK;
        uint32_t dA = sdst + stage * STAGE_BYTES;
        uint32_t dB = dA + PLANE_BYTES;
        #pragma unroll
        for (int r = 0; r < 4; ++r) {
            CP_ASYNC16(dA + r * (32 * ROWB), sA + (size_t)(32 * r) * LDK);
            CP_ASYNC16(dB + r * (32 * ROWB), sB + (size_t)(32 * r) * LDK);
        }
    };

    load_stage(0, 0);
    CP_COMMIT();
    load_stage(1, 1);
    CP_COMMIT();

    int cs = 0, ls = 2;
    for (int kt = 0; kt < KTILES; ++kt) {
        CP_WAIT1();
        __syncthreads();
        if (kt + 2 < KTILES) load_stage(ls, kt + 2);
        CP_COMMIT();

        const uint32_t stg = sbase + cs * STAGE_BYTES;
        uint32_t af[2][2][4];
        LDSM4(af[0][0], stg + a_row + soff[0]);
        LDSM4(af[0][1], stg + a_row + 2048 + soff[0]);

        #pragma unroll
        for (int s = 0; s < 4; ++s) {
            const int cur = s & 1, nxt = cur ^ 1;
            uint32_t bf[4][4];
            #pragma unroll
            for (int g = 0; g < 4; ++g)
                LDSM4(bf[g], stg + PLANE_BYTES + b_row + g * 2048 + soff[s]);
            if (s < 3) {
                LDSM4(af[nxt][0], stg + a_row + soff[s + 1]);
                LDSM4(af[nxt][1], stg + a_row + 2048 + soff[s + 1]);
            }
            #pragma unroll
            for (int g = 0; g < 4; ++g) {
                MMAF16(acc[0][2 * g],     af[cur][0], bf[g][0], bf[g][2]);
                MMAF16(acc[1][2 * g],     af[cur][1], bf[g][0], bf[g][2]);
                MMAF16(acc[0][2 * g + 1], af[cur][0], bf[g][1], bf[g][3]);
                MMAF16(acc[1][2 * g + 1], af[cur][1], bf[g][1], bf[g][3]);
            }
        }
        cs = (cs == 2) ? 0 : cs + 1;
        ls = (ls == 2) ? 0 : ls + 1;
    }

    const int r0 = m0 + wm * 32 + (lane >> 2);
    const int c0 = n0 + wn * 64 + (lane & 3) * 2;
    #pragma unroll
    for (int mt = 0; mt < 2; ++mt)
        #pragma unroll
        for (int nt = 0; nt < 8; ++nt) {
            int row = r0 + mt * 16;
            int col = c0 + nt * 8;
            *(float2*)&D[(size_t)row * NDIM + col] =
                make_float2(acc[mt][nt][0], acc[mt][nt][1]);
            *(float2*)&D[(size_t)(row + 8) * NDIM + col] =
                make_float2(acc[mt][nt][2], acc[mt][nt][3]);
        }
}

struct FusedArgs {
    const f16 *A[4], *B[4];
    float* D[4];
    const f16 *PA;            // patch basis [PR x 2048]
};

// Merged launch: bid<1024 -> main tiles; bid>=1024 -> patch split-K tiles.
// Patch: 256 CTAs = 4 z-chunks x 2 m-tiles x 32 n-tiles, each K=512 (8 ktiles).
__global__ void __launch_bounds__(256, 2) gemm_fused_kernel(FusedArgs a) {
    int bid = blockIdx.x;
    if (bid < 1024) {
        int z = bid >> 8;
        gemm_core<16, 1024>(a.A[z], a.B[z], a.D[z],
                            ((bid >> 5) & 7) * BM, (bid & 31) * BN);
    } else {
        int p = bid - 1024;
        int z = p >> 6;
        int rem = p & 63;
        gemm_core<8, 2048>(a.PA + z * 512, g_big + z * 512,
                           g_patchP + (size_t)z * PR * NDIM,
                           (rem >> 5) * BM, (rem & 31) * BN);
    }
}

// ---------------------------------------------------------------------------
// outer combine, stage 1 (sin): mirror fold inline, emits stage-2 operands.
// ---------------------------------------------------------------------------
__global__ void outer_combine1_kernel() {
    int t = blockIdx.x * 256 + threadIdx.x;   // 2048*256 threads
    int v = t >> 8;
    int j = t & 255;                          // p block [16j, 16j+16)
    const float sign = 1.0f;
    int vr = (v < 1024) ? v : 2047 - v;
    float a0 = (v < 1024) ? 1.0f : -sign;
    float a1 = (v < 1024) ? 1.0f : sign;
    size_t rowG = ((size_t)vr << 12) + 16 * j;

    float E[16], O[16];
    #pragma unroll
    for (int c = 0; c < 4; ++c) {
        float4 f0 = *(const float4*)(g_G0 + rowG + 4 * c);
        float4 f1 = *(const float4*)(g_G1 + rowG + 4 * c);
        E[4 * c]     = a0 * f0.x + a1 * f1.x;
        E[4 * c + 1] = a0 * f0.y + a1 * f1.y;
        E[4 * c + 2] = a0 * f0.z + a1 * f1.z;
        E[4 * c + 3] = a0 * f0.w + a1 * f1.w;
    }
    float En = (j > 0) ? (a0 * g_G0[rowG - 1] + a1 * g_G1[rowG - 1]) : 0.0f;
    float On;
    if (v < V0) {
        float r = 0.5f / cospif((2.0f * v + 1.0f) * (1.0f / 8192.0f));
        float s = (v & 1) ? -1.0f : 1.0f;
        #pragma unroll
        for (int c = 0; c < 4; ++c) {
            float4 f2 = *(const float4*)(g_G2 + rowG + 4 * c);
            float4 f3 = *(const float4*)(g_G3 + rowG + 4 * c);
            float4 b = *(const float4*)(g_b + 16 * j + 4 * c);
            O[4 * c]     = r * (a0 * f2.x + a1 * f3.x + s * b.x);
            O[4 * c + 1] = r * (a0 * f2.y + a1 * f3.y + s * b.y);
            O[4 * c + 2] = r * (a0 * f2.z + a1 * f3.z + s * b.z);
            O[4 * c + 3] = r * (a0 * f2.w + a1 * f3.w + s * b.w);
        }
        On = (j > 0)
           ? r * (a0 * g_G2[rowG - 1] + a1 * g_G3[rowG - 1] + s * g_b[16 * j - 1])
           : 0.0f;
    } else {
        size_t rowP = ((size_t)(v - V0) << 12) + 16 * j;
        #pragma unroll
        for (int m = 0; m < 16; ++m) O[m] = 0.0f;
        On = 0.0f;
        #pragma unroll
        for (int z = 0; z < PSPLIT; ++z) {
            size_t base = (size_t)z * PR * NDIM + rowP;
            #pragma unroll
            for (int c = 0; c < 4; ++c) {
                float4 f = *(const float4*)(g_patchP + base + 4 * c);
                O[4 * c] += f.x; O[4 * c + 1] += f.y;
                O[4 * c + 2] += f.z; O[4 * c + 3] += f.w;
            }
            if (j > 0) On += g_patchP[base - 1];
        }
    }

    #pragma unroll
    for (int half = 0; half < 2; ++half) {
        int row = half ? (4095 - v) : v;
        float yt[16], ytn;
        if (half == 0) {
            #pragma unroll
            for (int m = 0; m < 16; ++m) yt[m] = E[m] + O[m];
            ytn = En + On;
        } else {
            #pragma unroll
            for (int m = 0; m < 16; ++m) yt[m] = O[m] - E[m];
            ytn = On - En;
        }
        float yto[8], wc[8];
        #pragma unroll
        for (int k = 0; k < 8; ++k) yto[k] = yt[2 * k + 1];
        wc[0] = yto[0] + ytn;
        #pragma unroll
        for (int k = 1; k < 8; ++k) wc[k] = yto[k] + yto[k - 1];

        size_t o4 = ((size_t)row << 10) + 4 * j;
        size_t o8 = ((size_t)row << 11) + 8 * j;
        *(uint32_t*)(g_op0 + o4)     = pack_h2(yt[0], yt[4]);
        *(uint32_t*)(g_op0 + o4 + 2) = pack_h2(yt[8], yt[12]);
        *(uint32_t*)(g_op1 + o4)     = pack_h2(yt[2], yt[6]);
        *(uint32_t*)(g_op1 + o4 + 2) = pack_h2(yt[10], yt[14]);
        *(uint32_t*)(g_op2 + o4)     = pack_h2(wc[0], wc[2]);
        *(uint32_t*)(g_op2 + o4 + 2) = pack_h2(wc[4], wc[6]);
        *(uint32_t*)(g_op3 + o4)     = pack_h2(wc[1], wc[3]);
        *(uint32_t*)(g_op3 + o4 + 2) = pack_h2(wc[5], wc[7]);
        #pragma unroll
        for (int k = 0; k < 8; k += 2)
            *(uint32_t*)(g_big + o8 + k) = pack_h2(yto[k], yto[k + 1]);
    }
}

// stage 2 (cos, sign=-1, no boundary): out[u]=E+O; out[4095-u]=E-O
__global__ void outer_combine2_kernel(float* __restrict__ out) {
    int t = blockIdx.x * 256 + threadIdx.x;   // 2048*1024 threads
    int u = t >> 10;
    int j = t & 1023;
    const float sign = -1.0f;
    int ur = (u < 1024) ? u : 2047 - u;
    float a0 = (u < 1024) ? 1.0f : -sign;
    float a1 = (u < 1024) ? 1.0f : sign;
    size_t rowG = ((size_t)ur << 12) + 4 * j;

    float4 f0 = *(const float4*)(g_G0 + rowG);
    float4 f1 = *(const float4*)(g_G1 + rowG);
    float4 e = make_float4(a0 * f0.x + a1 * f1.x, a0 * f0.y + a1 * f1.y,
                           a0 * f0.z + a1 * f1.z, a0 * f0.w + a1 * f1.w);
    float4 o;
    if (u < V0) {
        float r = 0.5f / cospif((2.0f * u + 1.0f) * (1.0f / 8192.0f));
        float4 f2 = *(const float4*)(g_G2 + rowG);
        float4 f3 = *(const float4*)(g_G3 + rowG);
        o = make_float4(r * (a0 * f2.x + a1 * f3.x), r * (a0 * f2.y + a1 * f3.y),
                        r * (a0 * f2.z + a1 * f3.z), r * (a0 * f2.w + a1 * f3.w));
    } else {
        size_t rowP = ((size_t)(u - V0) << 12) + 4 * j;
        o = make_float4(0.f, 0.f, 0.f, 0.f);
        #pragma unroll
        for (int z = 0; z < PSPLIT; ++z) {
            float4 f = *(const float4*)(g_patchP + (size_t)z * PR * NDIM + rowP);
            o.x += f.x; o.y += f.y; o.z += f.z; o.w += f.w;
        }
    }
    *(float4*)(out + ((size_t)u << 12) + 4 * j) =
        make_float4(e.x + o.x, e.y + o.y, e.z + o.z, e.w + o.w);
    *(float4*)(out + ((size_t)(4095 - u) << 12) + 4 * j) =
        make_float4(e.x - o.x, e.y - o.y, e.z - o.z, e.w - o.w);
}

// ---------------------------------------------------------------------------
extern "C" void kernel_launch(void* const* d_in, const int* in_sizes, int n_in,
                              void* d_out, int out_size) {
    const float* x = (const float*)d_in[0];
    float* out = (float*)d_out;

    f16 *op0, *op1, *op2, *op3;
    f16 *Se2, *So2, *Ce2, *Co2, *SoP, *CoP;
    float *G0, *G1, *G2, *G3;
    cudaGetSymbolAddress((void**)&op0, g_op0);
    cudaGetSymbolAddress((void**)&op1, g_op1);
    cudaGetSymbolAddress((void**)&op2, g_op2);
    cudaGetSymbolAddress((void**)&op3, g_op3);
    cudaGetSymbolAddress((void**)&Se2, g_Se2);
    cudaGetSymbolAddress((void**)&So2, g_So2);
    cudaGetSymbolAddress((void**)&Ce2, g_Ce2);
    cudaGetSymbolAddress((void**)&Co2, g_Co2);
    cudaGetSymbolAddress((void**)&SoP, g_SoP);
    cudaGetSymbolAddress((void**)&CoP, g_CoP);
    cudaGetSymbolAddress((void**)&G0, g_G0); cudaGetSymbolAddress((void**)&G1, g_G1);
    cudaGetSymbolAddress((void**)&G2, g_G2); cudaGetSymbolAddress((void**)&G3, g_G3);

    cudaFuncSetAttribute(gemm_fused_kernel,
                         cudaFuncAttributeMaxDynamicSharedMemorySize, SMEM_BYTES);

    build_table_kernel<<<64, 256>>>();
    gen_basis_inner<<<(1024 * 512) / 256, 256>>>();
    gen_basis_patch<<<(PR * 1024) / 256, 256>>>();
    split_x2_kernel<<<(NDIM * 256) / 256, 256>>>(x);

    // ---- stage 1 (sin along q) ----
    FusedArgs a1;
    a1.A[0] = Se2; a1.B[0] = op0; a1.D[0] = G0;
    a1.A[1] = So2; a1.B[1] = op1; a1.D[1] = G1;
    a1.A[2] = Se2; a1.B[2] = op2; a1.D[2] = G2;
    a1.A[3] = So2; a1.B[3] = op3; a1.D[3] = G3;
    a1.PA = SoP;
    gemm_fused_kernel<<<1024 + 256, 256, SMEM_BYTES>>>(a1);
    outer_combine1_kernel<<<(2048 * 256) / 256, 256>>>();

    // ---- stage 2 (cos along p) ----
    FusedArgs a2;
    a2.A[0] = Ce2; a2.B[0] = op0; a2.D[0] = G0;
    a2.A[1] = Co2; a2.B[1] = op1; a2.D[1] = G1;
    a2.A[2] = Ce2; a2.B[2] = op2; a2.D[2] = G2;
    a2.A[3] = Co2; a2.B[3] = op3; a2.D[3] = G3;
    a2.PA = CoP;
    gemm_fused_kernel<<<1024 + 256, 256, SMEM_BYTES>>>(a2);
    outer_combine2_kernel<<<(2048 * 1024) / 256, 256>>>(out);
}

// round 16
// speedup vs baseline: 1.6752x; 1.0088x over previous
#include <cuda_runtime.h>
#include <cuda_fp16.h>
#include <cstdint>

// ============================================================================
// IDCST2: out = C0 @ x @ S1^T, M=N=4096 fp32.  Plain-sm_103 tensor path
// (mma.sync m16n8k16 f16 + ldmatrix + cp.async).
// R6/R7: two-level fast transform (parity fold + Lee), dense patch rows,
//        fused combines, patch GEMM merged into main launch.
// R9:  single-fp16 operands, 1 MMA per MAC; Lee cap V0=1792 (r<=2.56).
// R10: BK=64, 128B rows (chunk^=row&7 swizzle), A-fragment double buffering.
// R12: non-persistent launch; patch split-K = 4.   [311.4 -> 309.7 us]
// R15: k-tile head reorder: issue s=0 fragment LDSMs (2A+4B) immediately
//      after the barrier, BEFORE the cp.async prefetch issues, so the LSU
//      issue burst overlaps LDSM latency instead of preceding it.
//      (Note: pre-barrier LDSM prefetch was considered and rejected —
//      cp.async cross-thread visibility requires barrier-after-wait.)
// ============================================================================

#define NDIM 4096
typedef __half f16;

static constexpr int BM = 128;
static constexpr int BN = 128;
static constexpr int BK = 64;
static constexpr int V0 = 1792;           // patch start row
static constexpr int PR = 256;            // patch rows (2048 - V0)
static constexpr int PSPLIT = 4;          // patch split-K chunks

static constexpr int ROWB        = 128;             // 64 f16 = 128B rows
static constexpr int PLANE_BYTES = 128 * ROWB;      // 16384
static constexpr int STAGE_BYTES = 2 * PLANE_BYTES; // 32768 (A, B)
static constexpr int NSTAGE      = 3;
static constexpr int SMEM_BYTES  = NSTAGE * STAGE_BYTES; // 98304

// -------------------- device scratch ----------------------------------------
__device__ float g_table[16384];
__device__ f16 g_op0[(size_t)NDIM * 1024];
__device__ f16 g_op1[(size_t)NDIM * 1024];
__device__ f16 g_op2[(size_t)NDIM * 1024];
__device__ f16 g_op3[(size_t)NDIM * 1024];
__device__ f16 g_big[(size_t)NDIM * 2048];
__device__ float g_b[NDIM];               // boundary vector (stage 1 only)
__device__ f16 g_Se2[1024 * 1024];
__device__ f16 g_So2[1024 * 1024];
__device__ f16 g_Ce2[1024 * 1024];
__device__ f16 g_Co2[1024 * 1024];
__device__ f16 g_SoP[PR * 2048];
__device__ f16 g_CoP[PR * 2048];
__device__ float g_G0[(size_t)1024 * NDIM];
__device__ float g_G1[(size_t)1024 * NDIM];
__device__ float g_G2[(size_t)1024 * NDIM];
__device__ float g_G3[(size_t)1024 * NDIM];
__device__ float g_patchP[(size_t)PSPLIT * PR * NDIM];

// -------------------- helpers ------------------------------------------------
__device__ __forceinline__ uint32_t smem_to_u32(const void* p) {
    uint32_t a;
    asm("{ .reg .u64 t; cvta.to.shared.u64 t, %1; cvt.u32.u64 %0, t; }" : "=r"(a) : "l"(p));
    return a;
}

__device__ __forceinline__ uint32_t pack_h2(float x, float y) {
    __half2 H = __floats2half2_rn(x, y);
    return *(uint32_t*)&H;
}

#define CP_ASYNC16(dst, src) \
    asm volatile("cp.async.cg.shared.global [%0], [%1], 16;" :: "r"(dst), "l"(src))
#define CP_COMMIT() asm volatile("cp.async.commit_group;" ::: "memory")
#define CP_WAIT1()  asm volatile("cp.async.wait_group 1;"  ::: "memory")

#define LDSM4(r, addr) \
    asm volatile("ldmatrix.sync.aligned.m8n8.x4.shared.b16 {%0,%1,%2,%3}, [%4];" \
                 : "=r"((r)[0]), "=r"((r)[1]), "=r"((r)[2]), "=r"((r)[3]) : "r"(addr))

#define MMAF16(d, a, b0, b1) \
    asm volatile("mma.sync.aligned.m16n8k16.row.col.f32.f16.f16.f32 " \
                 "{%0,%1,%2,%3}, {%4,%5,%6,%7}, {%8,%9}, {%0,%1,%2,%3};" \
                 : "+f"((d)[0]), "+f"((d)[1]), "+f"((d)[2]), "+f"((d)[3]) \
                 : "r"((a)[0]), "r"((a)[1]), "r"((a)[2]), "r"((a)[3]), "r"(b0), "r"(b1))

// ---------------------------------------------------------------------------
__global__ void build_table_kernel() {
    int r = blockIdx.x * 256 + threadIdx.x;
    float s, c;
    sincospif((float)r * (1.0f / 8192.0f), &s, &c);
    g_table[r] = s;
}

// inner bases: Se2[i,q]=sin(pi(2i+1)q/2048); So2[i,q]=sin(pi(2i+1)(2q+1)/4096)
__global__ void gen_basis_inner() {
    int t = blockIdx.x * 256 + threadIdx.x;   // 1024*512 threads
    int i = t >> 9;
    int j2 = (t & 511) << 1;
    int step = 4 * (2 * i + 1);
    int a0 = ((2 * i + 1) * 4 * j2) & 16383;
    int a1 = (a0 + step) & 16383;
    int b0 = (2 * (2 * i + 1) * (2 * j2 + 1)) & 16383;
    int b1 = (b0 + step) & 16383;
    size_t off = ((size_t)i << 10) + j2;
    *(uint32_t*)(g_Se2 + off) = pack_h2(g_table[a0], g_table[a1]);
    *(uint32_t*)(g_So2 + off) = pack_h2(g_table[b0], g_table[b1]);
    *(uint32_t*)(g_Ce2 + off) =
        pack_h2(g_table[(a0 + 4096) & 16383], g_table[(a1 + 4096) & 16383]);
    *(uint32_t*)(g_Co2 + off) =
        pack_h2(g_table[(b0 + 4096) & 16383], g_table[(b1 + 4096) & 16383]);
}

// patch bases: SoP[i,q] = sin(pi(2(V0+i)+1)(2q+1)/8192), CoP = cos version
__global__ void gen_basis_patch() {
    int t = blockIdx.x * 256 + threadIdx.x;   // PR*1024 threads
    int i = t >> 10;
    int j2 = (t & 1023) << 1;
    int M = 2 * (V0 + i) + 1;
    int a0 = (M * (2 * j2 + 1)) & 16383;
    int a1 = (a0 + 2 * M) & 16383;
    size_t off = ((size_t)i << 11) + j2;
    *(uint32_t*)(g_SoP + off) = pack_h2(g_table[a0], g_table[a1]);
    *(uint32_t*)(g_CoP + off) =
        pack_h2(g_table[(a0 + 4096) & 16383], g_table[(a1 + 4096) & 16383]);
}

// ---------------------------------------------------------------------------
__global__ void split_x2_kernel(const float* __restrict__ x) {
    int t = blockIdx.x * 256 + threadIdx.x;   // 4096*256 threads
    int p = t >> 8;
    int j = t & 255;
    const float* xr = x + (size_t)p * NDIM + 16 * j;
    float v[16];
    #pragma unroll
    for (int c = 0; c < 4; ++c) {
        float4 f = *(const float4*)(xr + 4 * c);
        v[4 * c] = f.x; v[4 * c + 1] = f.y; v[4 * c + 2] = f.z; v[4 * c + 3] = f.w;
    }
    float xm1 = (j > 0) ? xr[-1] : 0.0f;

    float xo[8], w[8];
    #pragma unroll
    for (int k = 0; k < 8; ++k) xo[k] = v[2 * k + 1];
    w[0] = xo[0] + xm1;
    #pragma unroll
    for (int k = 1; k < 8; ++k) w[k] = xo[k] + xo[k - 1];

    size_t o4 = ((size_t)p << 10) + 4 * j;
    size_t o8 = ((size_t)p << 11) + 8 * j;
    *(uint32_t*)(g_op0 + o4)     = pack_h2(v[0], v[4]);
    *(uint32_t*)(g_op0 + o4 + 2) = pack_h2(v[8], v[12]);
    *(uint32_t*)(g_op1 + o4)     = pack_h2(v[2], v[6]);
    *(uint32_t*)(g_op1 + o4 + 2) = pack_h2(v[10], v[14]);
    *(uint32_t*)(g_op2 + o4)     = pack_h2(w[0], w[2]);
    *(uint32_t*)(g_op2 + o4 + 2) = pack_h2(w[4], w[6]);
    *(uint32_t*)(g_op3 + o4)     = pack_h2(w[1], w[3]);
    *(uint32_t*)(g_op3 + o4 + 2) = pack_h2(w[5], w[7]);
    #pragma unroll
    for (int k = 0; k < 8; k += 2)
        *(uint32_t*)(g_big + o8 + k) = pack_h2(xo[k], xo[k + 1]);
    if (j == 255) g_b[p] = v[15];
}

// ---------------------------------------------------------------------------
// GEMM core: D[m,n] = sum_k A[m,k]*B[n,k]; both operands single fp16.
// BK=64: 4 k16 steps per k-tile, one sync per k-tile, 3-stage cp.async.
// smem: 128B rows, swizzle chunk(16B) ^= row&7.
// R15 head order per k-tile: wait -> sync -> s=0 LDSMs (2A+4B) ->
// cp.async prefetch -> commit -> s-loop (B reloaded per s>0; A dbl-buffered).
// ---------------------------------------------------------------------------
template<int KTILES, int LDK>
__device__ __forceinline__ void gemm_core(
    const f16* __restrict__ A, const f16* __restrict__ B,
    float* __restrict__ D, int m0, int n0) {
    extern __shared__ char smem[];
    const uint32_t sbase = smem_to_u32(smem);
    const int tid = threadIdx.x;
    const int lane = tid & 31;
    const int wid = tid >> 5;
    const int wm = wid & 3;
    const int wn = wid >> 2;

    const int lr = tid >> 3;       // 0..31
    const int lc = tid & 7;        // 0..7
    const f16* gsrcA = A + (size_t)(m0 + lr) * LDK + lc * 8;
    const f16* gsrcB = B + (size_t)(n0 + lr) * LDK + lc * 8;
    const uint32_t sdst = sbase + lr * ROWB + (uint32_t)((lc ^ (lr & 7)) << 4);

    uint32_t soff[4];
    #pragma unroll
    for (int s = 0; s < 4; ++s)
        soff[s] = (uint32_t)(((((s << 1) + (lane >> 4)) ^ (lane & 7)) << 4));
    const uint32_t a_row = (uint32_t)((wm * 32 + (lane & 15)) * ROWB);
    const uint32_t b_row = (uint32_t)((wn * 64 + (lane & 15)) * ROWB);

    float acc[2][8][4];
    #pragma unroll
    for (int a = 0; a < 2; ++a)
        #pragma unroll
        for (int b = 0; b < 8; ++b)
            #pragma unroll
            for (int c = 0; c < 4; ++c) acc[a][b][c] = 0.0f;

    auto load_stage = [&](int stage, int kt) {
        const f16* sA = gsrcA + kt * BK;
        const f16* sB = gsrcB + kt * BK;
        uint32_t dA = sdst + stage * STAGE_BYTES;
        uint32_t dB = dA + PLANE_BYTES;
        #pragma unroll
        for (int r = 0; r < 4; ++r) {
            CP_ASYNC16(dA + r * (32 * ROWB), sA + (size_t)(32 * r) * LDK);
            CP_ASYNC16(dB + r * (32 * ROWB), sB + (size_t)(32 * r) * LDK);
        }
    };

    load_stage(0, 0);
    CP_COMMIT();
    load_stage(1, 1);
    CP_COMMIT();

    int cs = 0, ls = 2;
    for (int kt = 0; kt < KTILES; ++kt) {
        const uint32_t stg = sbase + cs * STAGE_BYTES;
        CP_WAIT1();
        __syncthreads();

        // s=0 fragment loads FIRST: start the LDSM latency chain immediately,
        // then overlap the cp.async issue burst + commit under it.
        uint32_t af[2][2][4];
        uint32_t bf[4][4];
        LDSM4(af[0][0], stg + a_row + soff[0]);
        LDSM4(af[0][1], stg + a_row + 2048 + soff[0]);
        #pragma unroll
        for (int g = 0; g < 4; ++g)
            LDSM4(bf[g], stg + PLANE_BYTES + b_row + g * 2048 + soff[0]);

        if (kt + 2 < KTILES) load_stage(ls, kt + 2);
        CP_COMMIT();

        #pragma unroll
        for (int s = 0; s < 4; ++s) {
            const int cur = s & 1, nxt = cur ^ 1;
            if (s > 0) {
                #pragma unroll
                for (int g = 0; g < 4; ++g)
                    LDSM4(bf[g], stg + PLANE_BYTES + b_row + g * 2048 + soff[s]);
            }
            if (s < 3) {
                LDSM4(af[nxt][0], stg + a_row + soff[s + 1]);
                LDSM4(af[nxt][1], stg + a_row + 2048 + soff[s + 1]);
            }
            #pragma unroll
            for (int g = 0; g < 4; ++g) {
                MMAF16(acc[0][2 * g],     af[cur][0], bf[g][0], bf[g][2]);
                MMAF16(acc[1][2 * g],     af[cur][1], bf[g][0], bf[g][2]);
                MMAF16(acc[0][2 * g + 1], af[cur][0], bf[g][1], bf[g][3]);
                MMAF16(acc[1][2 * g + 1], af[cur][1], bf[g][1], bf[g][3]);
            }
        }
        cs = (cs == 2) ? 0 : cs + 1;
        ls = (ls == 2) ? 0 : ls + 1;
    }

    const int r0 = m0 + wm * 32 + (lane >> 2);
    const int c0 = n0 + wn * 64 + (lane & 3) * 2;
    #pragma unroll
    for (int mt = 0; mt < 2; ++mt)
        #pragma unroll
        for (int nt = 0; nt < 8; ++nt) {
            int row = r0 + mt * 16;
            int col = c0 + nt * 8;
            *(float2*)&D[(size_t)row * NDIM + col] =
                make_float2(acc[mt][nt][0], acc[mt][nt][1]);
            *(float2*)&D[(size_t)(row + 8) * NDIM + col] =
                make_float2(acc[mt][nt][2], acc[mt][nt][3]);
        }
}

struct FusedArgs {
    const f16 *A[4], *B[4];
    float* D[4];
    const f16 *PA;            // patch basis [PR x 2048]
};

// Merged launch: bid<1024 -> main tiles; bid>=1024 -> patch split-K tiles.
// Patch: 256 CTAs = 4 z-chunks x 2 m-tiles x 32 n-tiles, each K=512 (8 ktiles).
__global__ void __launch_bounds__(256, 2) gemm_fused_kernel(FusedArgs a) {
    int bid = blockIdx.x;
    if (bid < 1024) {
        int z = bid >> 8;
        gemm_core<16, 1024>(a.A[z], a.B[z], a.D[z],
                            ((bid >> 5) & 7) * BM, (bid & 31) * BN);
    } else {
        int p = bid - 1024;
        int z = p >> 6;
        int rem = p & 63;
        gemm_core<8, 2048>(a.PA + z * 512, g_big + z * 512,
                           g_patchP + (size_t)z * PR * NDIM,
                           (rem >> 5) * BM, (rem & 31) * BN);
    }
}

// ---------------------------------------------------------------------------
// outer combine, stage 1 (sin): mirror fold inline, emits stage-2 operands.
// ---------------------------------------------------------------------------
__global__ void outer_combine1_kernel() {
    int t = blockIdx.x * 256 + threadIdx.x;   // 2048*256 threads
    int v = t >> 8;
    int j = t & 255;                          // p block [16j, 16j+16)
    const float sign = 1.0f;
    int vr = (v < 1024) ? v : 2047 - v;
    float a0 = (v < 1024) ? 1.0f : -sign;
    float a1 = (v < 1024) ? 1.0f : sign;
    size_t rowG = ((size_t)vr << 12) + 16 * j;

    float E[16], O[16];
    #pragma unroll
    for (int c = 0; c < 4; ++c) {
        float4 f0 = *(const float4*)(g_G0 + rowG + 4 * c);
        float4 f1 = *(const float4*)(g_G1 + rowG + 4 * c);
        E[4 * c]     = a0 * f0.x + a1 * f1.x;
        E[4 * c + 1] = a0 * f0.y + a1 * f1.y;
        E[4 * c + 2] = a0 * f0.z + a1 * f1.z;
        E[4 * c + 3] = a0 * f0.w + a1 * f1.w;
    }
    float En = (j > 0) ? (a0 * g_G0[rowG - 1] + a1 * g_G1[rowG - 1]) : 0.0f;
    float On;
    if (v < V0) {
        float r = 0.5f / cospif((2.0f * v + 1.0f) * (1.0f / 8192.0f));
        float s = (v & 1) ? -1.0f : 1.0f;
        #pragma unroll
        for (int c = 0; c < 4; ++c) {
            float4 f2 = *(const float4*)(g_G2 + rowG + 4 * c);
            float4 f3 = *(const float4*)(g_G3 + rowG + 4 * c);
            float4 b = *(const float4*)(g_b + 16 * j + 4 * c);
            O[4 * c]     = r * (a0 * f2.x + a1 * f3.x + s * b.x);
            O[4 * c + 1] = r * (a0 * f2.y + a1 * f3.y + s * b.y);
            O[4 * c + 2] = r * (a0 * f2.z + a1 * f3.z + s * b.z);
            O[4 * c + 3] = r * (a0 * f2.w + a1 * f3.w + s * b.w);
        }
        On = (j > 0)
           ? r * (a0 * g_G2[rowG - 1] + a1 * g_G3[rowG - 1] + s * g_b[16 * j - 1])
           : 0.0f;
    } else {
        size_t rowP = ((size_t)(v - V0) << 12) + 16 * j;
        #pragma unroll
        for (int m = 0; m < 16; ++m) O[m] = 0.0f;
        On = 0.0f;
        #pragma unroll
        for (int z = 0; z < PSPLIT; ++z) {
            size_t base = (size_t)z * PR * NDIM + rowP;
            #pragma unroll
            for (int c = 0; c < 4; ++c) {
                float4 f = *(const float4*)(g_patchP + base + 4 * c);
                O[4 * c] += f.x; O[4 * c + 1] += f.y;
                O[4 * c + 2] += f.z; O[4 * c + 3] += f.w;
            }
            if (j > 0) On += g_patchP[base - 1];
        }
    }

    #pragma unroll
    for (int half = 0; half < 2; ++half) {
        int row = half ? (4095 - v) : v;
        float yt[16], ytn;
        if (half == 0) {
            #pragma unroll
            for (int m = 0; m < 16; ++m) yt[m] = E[m] + O[m];
            ytn = En + On;
        } else {
            #pragma unroll
            for (int m = 0; m < 16; ++m) yt[m] = O[m] - E[m];
            ytn = On - En;
        }
        float yto[8], wc[8];
        #pragma unroll
        for (int k = 0; k < 8; ++k) yto[k] = yt[2 * k + 1];
        wc[0] = yto[0] + ytn;
        #pragma unroll
        for (int k = 1; k < 8; ++k) wc[k] = yto[k] + yto[k - 1];

        size_t o4 = ((size_t)row << 10) + 4 * j;
        size_t o8 = ((size_t)row << 11) + 8 * j;
        *(uint32_t*)(g_op0 + o4)     = pack_h2(yt[0], yt[4]);
        *(uint32_t*)(g_op0 + o4 + 2) = pack_h2(yt[8], yt[12]);
        *(uint32_t*)(g_op1 + o4)     = pack_h2(yt[2], yt[6]);
        *(uint32_t*)(g_op1 + o4 + 2) = pack_h2(yt[10], yt[14]);
        *(uint32_t*)(g_op2 + o4)     = pack_h2(wc[0], wc[2]);
        *(uint32_t*)(g_op2 + o4 + 2) = pack_h2(wc[4], wc[6]);
        *(uint32_t*)(g_op3 + o4)     = pack_h2(wc[1], wc[3]);
        *(uint32_t*)(g_op3 + o4 + 2) = pack_h2(wc[5], wc[7]);
        #pragma unroll
        for (int k = 0; k < 8; k += 2)
            *(uint32_t*)(g_big + o8 + k) = pack_h2(yto[k], yto[k + 1]);
    }
}

// stage 2 (cos, sign=-1, no boundary): out[u]=E+O; out[4095-u]=E-O
__global__ void outer_combine2_kernel(float* __restrict__ out) {
    int t = blockIdx.x * 256 + threadIdx.x;   // 2048*1024 threads
    int u = t >> 10;
    int j = t & 1023;
    const float sign = -1.0f;
    int ur = (u < 1024) ? u : 2047 - u;
    float a0 = (u < 1024) ? 1.0f : -sign;
    float a1 = (u < 1024) ? 1.0f : sign;
    size_t rowG = ((size_t)ur << 12) + 4 * j;

    float4 f0 = *(const float4*)(g_G0 + rowG);
    float4 f1 = *(const float4*)(g_G1 + rowG);
    float4 e = make_float4(a0 * f0.x + a1 * f1.x, a0 * f0.y + a1 * f1.y,
                           a0 * f0.z + a1 * f1.z, a0 * f0.w + a1 * f1.w);
    float4 o;
    if (u < V0) {
        float r = 0.5f / cospif((2.0f * u + 1.0f) * (1.0f / 8192.0f));
        float4 f2 = *(const float4*)(g_G2 + rowG);
        float4 f3 = *(const float4*)(g_G3 + rowG);
        o = make_float4(r * (a0 * f2.x + a1 * f3.x), r * (a0 * f2.y + a1 * f3.y),
                        r * (a0 * f2.z + a1 * f3.z), r * (a0 * f2.w + a1 * f3.w));
    } else {
        size_t rowP = ((size_t)(u - V0) << 12) + 4 * j;
        o = make_float4(0.f, 0.f, 0.f, 0.f);
        #pragma unroll
        for (int z = 0; z < PSPLIT; ++z) {
            float4 f = *(const float4*)(g_patchP + (size_t)z * PR * NDIM + rowP);
            o.x += f.x; o.y += f.y; o.z += f.z; o.w += f.w;
        }
    }
    *(float4*)(out + ((size_t)u << 12) + 4 * j) =
        make_float4(e.x + o.x, e.y + o.y, e.z + o.z, e.w + o.w);
    *(float4*)(out + ((size_t)(4095 - u) << 12) + 4 * j) =
        make_float4(e.x - o.x, e.y - o.y, e.z - o.z, e.w - o.w);
}

// ---------------------------------------------------------------------------
extern "C" void kernel_launch(void* const* d_in, const int* in_sizes, int n_in,
                              void* d_out, int out_size) {
    const float* x = (const float*)d_in[0];
    float* out = (float*)d_out;

    f16 *op0, *op1, *op2, *op3;
    f16 *Se2, *So2, *Ce2, *Co2, *SoP, *CoP;
    float *G0, *G1, *G2, *G3;
    cudaGetSymbolAddress((void**)&op0, g_op0);
    cudaGetSymbolAddress((void**)&op1, g_op1);
    cudaGetSymbolAddress((void**)&op2, g_op2);
    cudaGetSymbolAddress((void**)&op3, g_op3);
    cudaGetSymbolAddress((void**)&Se2, g_Se2);
    cudaGetSymbolAddress((void**)&So2, g_So2);
    cudaGetSymbolAddress((void**)&Ce2, g_Ce2);
    cudaGetSymbolAddress((void**)&Co2, g_Co2);
    cudaGetSymbolAddress((void**)&SoP, g_SoP);
    cudaGetSymbolAddress((void**)&CoP, g_CoP);
    cudaGetSymbolAddress((void**)&G0, g_G0); cudaGetSymbolAddress((void**)&G1, g_G1);
    cudaGetSymbolAddress((void**)&G2, g_G2); cudaGetSymbolAddress((void**)&G3, g_G3);

    cudaFuncSetAttribute(gemm_fused_kernel,
                         cudaFuncAttributeMaxDynamicSharedMemorySize, SMEM_BYTES);

    build_table_kernel<<<64, 256>>>();
    gen_basis_inner<<<(1024 * 512) / 256, 256>>>();
    gen_basis_patch<<<(PR * 1024) / 256, 256>>>();
    split_x2_kernel<<<(NDIM * 256) / 256, 256>>>(x);

    // ---- stage 1 (sin along q) ----
    FusedArgs a1;
    a1.A[0] = Se2; a1.B[0] = op0; a1.D[0] = G0;
    a1.A[1] = So2; a1.B[1] = op1; a1.D[1] = G1;
    a1.A[2] = Se2; a1.B[2] = op2; a1.D[2] = G2;
    a1.A[3] = So2; a1.B[3] = op3; a1.D[3] = G3;
    a1.PA = SoP;
    gemm_fused_kernel<<<1024 + 256, 256, SMEM_BYTES>>>(a1);
    outer_combine1_kernel<<<(2048 * 256) / 256, 256>>>();

    // ---- stage 2 (cos along p) ----
    FusedArgs a2;
    a2.A[0] = Ce2; a2.B[0] = op0; a2.D[0] = G0;
    a2.A[1] = Co2; a2.B[1] = op1; a2.D[1] = G1;
    a2.A[2] = Ce2; a2.B[2] = op2; a2.D[2] = G2;
    a2.A[3] = Co2; a2.B[3] = op3; a2.D[3] = G3;
    a2.PA = CoP;
    gemm_fused_kernel<<<1024 + 256, 256, SMEM_BYTES>>>(a2);
    outer_combine2_kernel<<<(2048 * 1024) / 256, 256>>>(out);
}

// round 17
// speedup vs baseline: 1.7178x; 1.0254x over previous
#include <cuda_runtime.h>
#include <cuda_fp16.h>
#include <cstdint>

// ============================================================================
// IDCST2: out = C0 @ x @ S1^T, M=N=4096 fp32.  Plain-sm_103 tensor path
// (mma.sync m16n8k16 f16 + ldmatrix + cp.async).
// R6/R7: two-level fast transform (parity fold + Lee), dense patch rows,
//        fused combines, patch GEMM merged into main launch.
// R9:  single-fp16 operands, 1 MMA per MAC; Lee cap V0=1792 (r<=2.56).
// R10: BK=64, 128B rows (chunk^=row&7 swizzle), A-fragment double buffering.
// R12: non-persistent launch; patch split-K = 4.
// R15: k-tile head reorder (s=0 LDSMs before cp.async issue).  [307.0 us]
// R16: single fused prologue kernel (basis-inner + basis-patch + split-x,
//      sincospif inline, no table) — removes 3 launch boundaries and lets
//      MUFU-bound basis blocks hide under bandwidth-bound split-x blocks.
// ============================================================================

#define NDIM 4096
typedef __half f16;

static constexpr int BM = 128;
static constexpr int BN = 128;
static constexpr int BK = 64;
static constexpr int V0 = 1792;           // patch start row
static constexpr int PR = 256;            // patch rows (2048 - V0)
static constexpr int PSPLIT = 4;          // patch split-K chunks

static constexpr int ROWB        = 128;             // 64 f16 = 128B rows
static constexpr int PLANE_BYTES = 128 * ROWB;      // 16384
static constexpr int STAGE_BYTES = 2 * PLANE_BYTES; // 32768 (A, B)
static constexpr int NSTAGE      = 3;
static constexpr int SMEM_BYTES  = NSTAGE * STAGE_BYTES; // 98304

// -------------------- device scratch ----------------------------------------
__device__ f16 g_op0[(size_t)NDIM * 1024];
__device__ f16 g_op1[(size_t)NDIM * 1024];
__device__ f16 g_op2[(size_t)NDIM * 1024];
__device__ f16 g_op3[(size_t)NDIM * 1024];
__device__ f16 g_big[(size_t)NDIM * 2048];
__device__ float g_b[NDIM];               // boundary vector (stage 1 only)
__device__ f16 g_Se2[1024 * 1024];
__device__ f16 g_So2[1024 * 1024];
__device__ f16 g_Ce2[1024 * 1024];
__device__ f16 g_Co2[1024 * 1024];
__device__ f16 g_SoP[PR * 2048];
__device__ f16 g_CoP[PR * 2048];
__device__ float g_G0[(size_t)1024 * NDIM];
__device__ float g_G1[(size_t)1024 * NDIM];
__device__ float g_G2[(size_t)1024 * NDIM];
__device__ float g_G3[(size_t)1024 * NDIM];
__device__ float g_patchP[(size_t)PSPLIT * PR * NDIM];

// -------------------- helpers ------------------------------------------------
__device__ __forceinline__ uint32_t smem_to_u32(const void* p) {
    uint32_t a;
    asm("{ .reg .u64 t; cvta.to.shared.u64 t, %1; cvt.u32.u64 %0, t; }" : "=r"(a) : "l"(p));
    return a;
}

__device__ __forceinline__ uint32_t pack_h2(float x, float y) {
    __half2 H = __floats2half2_rn(x, y);
    return *(uint32_t*)&H;
}

// sin & cos of (pi * r / 8192) for exact integer phase r
__device__ __forceinline__ void sc_phase(int r, float& s, float& c) {
    sincospif((float)r * (1.0f / 8192.0f), &s, &c);
}

#define CP_ASYNC16(dst, src) \
    asm volatile("cp.async.cg.shared.global [%0], [%1], 16;" :: "r"(dst), "l"(src))
#define CP_COMMIT() asm volatile("cp.async.commit_group;" ::: "memory")
#define CP_WAIT1()  asm volatile("cp.async.wait_group 1;"  ::: "memory")

#define LDSM4(r, addr) \
    asm volatile("ldmatrix.sync.aligned.m8n8.x4.shared.b16 {%0,%1,%2,%3}, [%4];" \
                 : "=r"((r)[0]), "=r"((r)[1]), "=r"((r)[2]), "=r"((r)[3]) : "r"(addr))

#define MMAF16(d, a, b0, b1) \
    asm volatile("mma.sync.aligned.m16n8k16.row.col.f32.f16.f16.f32 " \
                 "{%0,%1,%2,%3}, {%4,%5,%6,%7}, {%8,%9}, {%0,%1,%2,%3};" \
                 : "+f"((d)[0]), "+f"((d)[1]), "+f"((d)[2]), "+f"((d)[3]) \
                 : "r"((a)[0]), "r"((a)[1]), "r"((a)[2]), "r"((a)[3]), "r"(b0), "r"(b1))

// ---------------------------------------------------------------------------
// Fused prologue: one launch, three independent block families.
//   bid [0, 2048):      inner bases Se2/So2/Ce2/Co2 (sincospif inline)
//   bid [2048, 3072):   patch bases SoP/CoP
//   bid [3072, 7168):   split x -> op0..op3, big, b
// ---------------------------------------------------------------------------
__global__ void prologue_kernel(const float* __restrict__ x) {
    int bid = blockIdx.x;
    if (bid < 2048) {
        // ---- inner bases: Se2[i,q]=sin(pi(2i+1)q/2048) etc. ----
        int t = bid * 256 + threadIdx.x;      // 1024*512 threads
        int i = t >> 9;
        int j2 = (t & 511) << 1;
        int step = 4 * (2 * i + 1);
        int a0 = ((2 * i + 1) * 4 * j2) & 16383;
        int a1 = (a0 + step) & 16383;
        int b0 = (2 * (2 * i + 1) * (2 * j2 + 1)) & 16383;
        int b1 = (b0 + step) & 16383;
        float sA0, cA0, sA1, cA1, sB0, cB0, sB1, cB1;
        sc_phase(a0, sA0, cA0);
        sc_phase(a1, sA1, cA1);
        sc_phase(b0, sB0, cB0);
        sc_phase(b1, sB1, cB1);
        size_t off = ((size_t)i << 10) + j2;
        *(uint32_t*)(g_Se2 + off) = pack_h2(sA0, sA1);
        *(uint32_t*)(g_So2 + off) = pack_h2(sB0, sB1);
        *(uint32_t*)(g_Ce2 + off) = pack_h2(cA0, cA1);
        *(uint32_t*)(g_Co2 + off) = pack_h2(cB0, cB1);
    } else if (bid < 3072) {
        // ---- patch bases: SoP[i,q]=sin(pi(2(V0+i)+1)(2q+1)/8192) ----
        int t = (bid - 2048) * 256 + threadIdx.x;  // PR*1024 threads
        int i = t >> 10;
        int j2 = (t & 1023) << 1;
        int M = 2 * (V0 + i) + 1;
        int a0 = (M * (2 * j2 + 1)) & 16383;
        int a1 = (a0 + 2 * M) & 16383;
        float s0, c0, s1, c1;
        sc_phase(a0, s0, c0);
        sc_phase(a1, s1, c1);
        size_t off = ((size_t)i << 11) + j2;
        *(uint32_t*)(g_SoP + off) = pack_h2(s0, s1);
        *(uint32_t*)(g_CoP + off) = pack_h2(c0, c1);
    } else {
        // ---- split x by parity + pairsum ----
        int t = (bid - 3072) * 256 + threadIdx.x;  // 4096*256 threads
        int p = t >> 8;
        int j = t & 255;
        const float* xr = x + (size_t)p * NDIM + 16 * j;
        float v[16];
        #pragma unroll
        for (int c = 0; c < 4; ++c) {
            float4 f = *(const float4*)(xr + 4 * c);
            v[4 * c] = f.x; v[4 * c + 1] = f.y;
            v[4 * c + 2] = f.z; v[4 * c + 3] = f.w;
        }
        float xm1 = (j > 0) ? xr[-1] : 0.0f;

        float xo[8], w[8];
        #pragma unroll
        for (int k = 0; k < 8; ++k) xo[k] = v[2 * k + 1];
        w[0] = xo[0] + xm1;
        #pragma unroll
        for (int k = 1; k < 8; ++k) w[k] = xo[k] + xo[k - 1];

        size_t o4 = ((size_t)p << 10) + 4 * j;
        size_t o8 = ((size_t)p << 11) + 8 * j;
        *(uint32_t*)(g_op0 + o4)     = pack_h2(v[0], v[4]);
        *(uint32_t*)(g_op0 + o4 + 2) = pack_h2(v[8], v[12]);
        *(uint32_t*)(g_op1 + o4)     = pack_h2(v[2], v[6]);
        *(uint32_t*)(g_op1 + o4 + 2) = pack_h2(v[10], v[14]);
        *(uint32_t*)(g_op2 + o4)     = pack_h2(w[0], w[2]);
        *(uint32_t*)(g_op2 + o4 + 2) = pack_h2(w[4], w[6]);
        *(uint32_t*)(g_op3 + o4)     = pack_h2(w[1], w[3]);
        *(uint32_t*)(g_op3 + o4 + 2) = pack_h2(w[5], w[7]);
        #pragma unroll
        for (int k = 0; k < 8; k += 2)
            *(uint32_t*)(g_big + o8 + k) = pack_h2(xo[k], xo[k + 1]);
        if (j == 255) g_b[p] = v[15];
    }
}

// ---------------------------------------------------------------------------
// GEMM core: D[m,n] = sum_k A[m,k]*B[n,k]; both operands single fp16.
// BK=64: 4 k16 steps per k-tile, one sync per k-tile, 3-stage cp.async.
// smem: 128B rows, swizzle chunk(16B) ^= row&7.
// R15 head order per k-tile: wait -> sync -> s=0 LDSMs (2A+4B) ->
// cp.async prefetch -> commit -> s-loop (B reloaded per s>0; A dbl-buffered).
// ---------------------------------------------------------------------------
template<int KTILES, int LDK>
__device__ __forceinline__ void gemm_core(
    const f16* __restrict__ A, const f16* __restrict__ B,
    float* __restrict__ D, int m0, int n0) {
    extern __shared__ char smem[];
    const uint32_t sbase = smem_to_u32(smem);
    const int tid = threadIdx.x;
    const int lane = tid & 31;
    const int wid = tid >> 5;
    const int wm = wid & 3;
    const int wn = wid >> 2;

    const int lr = tid >> 3;       // 0..31
    const int lc = tid & 7;        // 0..7
    const f16* gsrcA = A + (size_t)(m0 + lr) * LDK + lc * 8;
    const f16* gsrcB = B + (size_t)(n0 + lr) * LDK + lc * 8;
    const uint32_t sdst = sbase + lr * ROWB + (uint32_t)((lc ^ (lr & 7)) << 4);

    uint32_t soff[4];
    #pragma unroll
    for (int s = 0; s < 4; ++s)
        soff[s] = (uint32_t)(((((s << 1) + (lane >> 4)) ^ (lane & 7)) << 4));
    const uint32_t a_row = (uint32_t)((wm * 32 + (lane & 15)) * ROWB);
    const uint32_t b_row = (uint32_t)((wn * 64 + (lane & 15)) * ROWB);

    float acc[2][8][4];
    #pragma unroll
    for (int a = 0; a < 2; ++a)
        #pragma unroll
        for (int b = 0; b < 8; ++b)
            #pragma unroll
            for (int c = 0; c < 4; ++c) acc[a][b][c] = 0.0f;

    auto load_stage = [&](int stage, int kt) {
        const f16* sA = gsrcA + kt * BK;
        const f16* sB = gsrcB + kt * BK;
        uint32_t dA = sdst + stage * STAGE_BYTES;
        uint32_t dB = dA + PLANE_BYTES;
        #pragma unroll
        for (int r = 0; r < 4; ++r) {
            CP_ASYNC16(dA + r * (32 * ROWB), sA + (size_t)(32 * r) * LDK);
            CP_ASYNC16(dB + r * (32 * ROWB), sB + (size_t)(32 * r) * LDK);
        }
    };

    load_stage(0, 0);
    CP_COMMIT();
    load_stage(1, 1);
    CP_COMMIT();

    int cs = 0, ls = 2;
    for (int kt = 0; kt < KTILES; ++kt) {
        const uint32_t stg = sbase + cs * STAGE_BYTES;
        CP_WAIT1();
        __syncthreads();

        // s=0 fragment loads first: start LDSM latency chain immediately,
        // overlap the cp.async issue burst + commit under it.
        uint32_t af[2][2][4];
        uint32_t bf[4][4];
        LDSM4(af[0][0], stg + a_row + soff[0]);
        LDSM4(af[0][1], stg + a_row + 2048 + soff[0]);
        #pragma unroll
        for (int g = 0; g < 4; ++g)
            LDSM4(bf[g], stg + PLANE_BYTES + b_row + g * 2048 + soff[0]);

        if (kt + 2 < KTILES) load_stage(ls, kt + 2);
        CP_COMMIT();

        #pragma unroll
        for (int s = 0; s < 4; ++s) {
            const int cur = s & 1, nxt = cur ^ 1;
            if (s > 0) {
                #pragma unroll
                for (int g = 0; g < 4; ++g)
                    LDSM4(bf[g], stg + PLANE_BYTES + b_row + g * 2048 + soff[s]);
            }
            if (s < 3) {
                LDSM4(af[nxt][0], stg + a_row + soff[s + 1]);
                LDSM4(af[nxt][1], stg + a_row + 2048 + soff[s + 1]);
            }
            #pragma unroll
            for (int g = 0; g < 4; ++g) {
                MMAF16(acc[0][2 * g],     af[cur][0], bf[g][0], bf[g][2]);
                MMAF16(acc[1][2 * g],     af[cur][1], bf[g][0], bf[g][2]);
                MMAF16(acc[0][2 * g + 1], af[cur][0], bf[g][1], bf[g][3]);
                MMAF16(acc[1][2 * g + 1], af[cur][1], bf[g][1], bf[g][3]);
            }
        }
        cs = (cs == 2) ? 0 : cs + 1;
        ls = (ls == 2) ? 0 : ls + 1;
    }

    const int r0 = m0 + wm * 32 + (lane >> 2);
    const int c0 = n0 + wn * 64 + (lane & 3) * 2;
    #pragma unroll
    for (int mt = 0; mt < 2; ++mt)
        #pragma unroll
        for (int nt = 0; nt < 8; ++nt) {
            int row = r0 + mt * 16;
            int col = c0 + nt * 8;
            *(float2*)&D[(size_t)row * NDIM + col] =
                make_float2(acc[mt][nt][0], acc[mt][nt][1]);
            *(float2*)&D[(size_t)(row + 8) * NDIM + col] =
                make_float2(acc[mt][nt][2], acc[mt][nt][3]);
        }
}

struct FusedArgs {
    const f16 *A[4], *B[4];
    float* D[4];
    const f16 *PA;            // patch basis [PR x 2048]
};

// Merged launch: bid<1024 -> main tiles; bid>=1024 -> patch split-K tiles.
// Patch: 256 CTAs = 4 z-chunks x 2 m-tiles x 32 n-tiles, each K=512 (8 ktiles).
__global__ void __launch_bounds__(256, 2) gemm_fused_kernel(FusedArgs a) {
    int bid = blockIdx.x;
    if (bid < 1024) {
        int z = bid >> 8;
        gemm_core<16, 1024>(a.A[z], a.B[z], a.D[z],
                            ((bid >> 5) & 7) * BM, (bid & 31) * BN);
    } else {
        int p = bid - 1024;
        int z = p >> 6;
        int rem = p & 63;
        gemm_core<8, 2048>(a.PA + z * 512, g_big + z * 512,
                           g_patchP + (size_t)z * PR * NDIM,
                           (rem >> 5) * BM, (rem & 31) * BN);
    }
}

// ---------------------------------------------------------------------------
// outer combine, stage 1 (sin): mirror fold inline, emits stage-2 operands.
// ---------------------------------------------------------------------------
__global__ void outer_combine1_kernel() {
    int t = blockIdx.x * 256 + threadIdx.x;   // 2048*256 threads
    int v = t >> 8;
    int j = t & 255;                          // p block [16j, 16j+16)
    const float sign = 1.0f;
    int vr = (v < 1024) ? v : 2047 - v;
    float a0 = (v < 1024) ? 1.0f : -sign;
    float a1 = (v < 1024) ? 1.0f : sign;
    size_t rowG = ((size_t)vr << 12) + 16 * j;

    float E[16], O[16];
    #pragma unroll
    for (int c = 0; c < 4; ++c) {
        float4 f0 = *(const float4*)(g_G0 + rowG + 4 * c);
        float4 f1 = *(const float4*)(g_G1 + rowG + 4 * c);
        E[4 * c]     = a0 * f0.x + a1 * f1.x;
        E[4 * c + 1] = a0 * f0.y + a1 * f1.y;
        E[4 * c + 2] = a0 * f0.z + a1 * f1.z;
        E[4 * c + 3] = a0 * f0.w + a1 * f1.w;
    }
    float En = (j > 0) ? (a0 * g_G0[rowG - 1] + a1 * g_G1[rowG - 1]) : 0.0f;
    float On;
    if (v < V0) {
        float r = 0.5f / cospif((2.0f * v + 1.0f) * (1.0f / 8192.0f));
        float s = (v & 1) ? -1.0f : 1.0f;
        #pragma unroll
        for (int c = 0; c < 4; ++c) {
            float4 f2 = *(const float4*)(g_G2 + rowG + 4 * c);
            float4 f3 = *(const float4*)(g_G3 + rowG + 4 * c);
            float4 b = *(const float4*)(g_b + 16 * j + 4 * c);
            O[4 * c]     = r * (a0 * f2.x + a1 * f3.x + s * b.x);
            O[4 * c + 1] = r * (a0 * f2.y + a1 * f3.y + s * b.y);
            O[4 * c + 2] = r * (a0 * f2.z + a1 * f3.z + s * b.z);
            O[4 * c + 3] = r * (a0 * f2.w + a1 * f3.w + s * b.w);
        }
        On = (j > 0)
           ? r * (a0 * g_G2[rowG - 1] + a1 * g_G3[rowG - 1] + s * g_b[16 * j - 1])
           : 0.0f;
    } else {
        size_t rowP = ((size_t)(v - V0) << 12) + 16 * j;
        #pragma unroll
        for (int m = 0; m < 16; ++m) O[m] = 0.0f;
        On = 0.0f;
        #pragma unroll
        for (int z = 0; z < PSPLIT; ++z) {
            size_t base = (size_t)z * PR * NDIM + rowP;
            #pragma unroll
            for (int c = 0; c < 4; ++c) {
                float4 f = *(const float4*)(g_patchP + base + 4 * c);
                O[4 * c] += f.x; O[4 * c + 1] += f.y;
                O[4 * c + 2] += f.z; O[4 * c + 3] += f.w;
            }
            if (j > 0) On += g_patchP[base - 1];
        }
    }

    #pragma unroll
    for (int half = 0; half < 2; ++half) {
        int row = half ? (4095 - v) : v;
        float yt[16], ytn;
        if (half == 0) {
            #pragma unroll
            for (int m = 0; m < 16; ++m) yt[m] = E[m] + O[m];
            ytn = En + On;
        } else {
            #pragma unroll
            for (int m = 0; m < 16; ++m) yt[m] = O[m] - E[m];
            ytn = On - En;
        }
        float yto[8], wc[8];
        #pragma unroll
        for (int k = 0; k < 8; ++k) yto[k] = yt[2 * k + 1];
        wc[0] = yto[0] + ytn;
        #pragma unroll
        for (int k = 1; k < 8; ++k) wc[k] = yto[k] + yto[k - 1];

        size_t o4 = ((size_t)row << 10) + 4 * j;
        size_t o8 = ((size_t)row << 11) + 8 * j;
        *(uint32_t*)(g_op0 + o4)     = pack_h2(yt[0], yt[4]);
        *(uint32_t*)(g_op0 + o4 + 2) = pack_h2(yt[8], yt[12]);
        *(uint32_t*)(g_op1 + o4)     = pack_h2(yt[2], yt[6]);
        *(uint32_t*)(g_op1 + o4 + 2) = pack_h2(yt[10], yt[14]);
        *(uint32_t*)(g_op2 + o4)     = pack_h2(wc[0], wc[2]);
        *(uint32_t*)(g_op2 + o4 + 2) = pack_h2(wc[4], wc[6]);
        *(uint32_t*)(g_op3 + o4)     = pack_h2(wc[1], wc[3]);
        *(uint32_t*)(g_op3 + o4 + 2) = pack_h2(wc[5], wc[7]);
        #pragma unroll
        for (int k = 0; k < 8; k += 2)
            *(uint32_t*)(g_big + o8 + k) = pack_h2(yto[k], yto[k + 1]);
    }
}

// stage 2 (cos, sign=-1, no boundary): out[u]=E+O; out[4095-u]=E-O
__global__ void outer_combine2_kernel(float* __restrict__ out) {
    int t = blockIdx.x * 256 + threadIdx.x;   // 2048*1024 threads
    int u = t >> 10;
    int j = t & 1023;
    const float sign = -1.0f;
    int ur = (u < 1024) ? u : 2047 - u;
    float a0 = (u < 1024) ? 1.0f : -sign;
    float a1 = (u < 1024) ? 1.0f : sign;
    size_t rowG = ((size_t)ur << 12) + 4 * j;

    float4 f0 = *(const float4*)(g_G0 + rowG);
    float4 f1 = *(const float4*)(g_G1 + rowG);
    float4 e = make_float4(a0 * f0.x + a1 * f1.x, a0 * f0.y + a1 * f1.y,
                           a0 * f0.z + a1 * f1.z, a0 * f0.w + a1 * f1.w);
    float4 o;
    if (u < V0) {
        float r = 0.5f / cospif((2.0f * u + 1.0f) * (1.0f / 8192.0f));
        float4 f2 = *(const float4*)(g_G2 + rowG);
        float4 f3 = *(const float4*)(g_G3 + rowG);
        o = make_float4(r * (a0 * f2.x + a1 * f3.x), r * (a0 * f2.y + a1 * f3.y),
                        r * (a0 * f2.z + a1 * f3.z), r * (a0 * f2.w + a1 * f3.w));
    } else {
        size_t rowP = ((size_t)(u - V0) << 12) + 4 * j;
        o = make_float4(0.f, 0.f, 0.f, 0.f);
        #pragma unroll
        for (int z = 0; z < PSPLIT; ++z) {
            float4 f = *(const float4*)(g_patchP + (size_t)z * PR * NDIM + rowP);
            o.x += f.x; o.y += f.y; o.z += f.z; o.w += f.w;
        }
    }
    *(float4*)(out + ((size_t)u << 12) + 4 * j) =
        make_float4(e.x + o.x, e.y + o.y, e.z + o.z, e.w + o.w);
    *(float4*)(out + ((size_t)(4095 - u) << 12) + 4 * j) =
        make_float4(e.x - o.x, e.y - o.y, e.z - o.z, e.w - o.w);
}

// ---------------------------------------------------------------------------
extern "C" void kernel_launch(void* const* d_in, const int* in_sizes, int n_in,
                              void* d_out, int out_size) {
    const float* x = (const float*)d_in[0];
    float* out = (float*)d_out;

    f16 *op0, *op1, *op2, *op3;
    f16 *Se2, *So2, *Ce2, *Co2, *SoP, *CoP;
    float *G0, *G1, *G2, *G3;
    cudaGetSymbolAddress((void**)&op0, g_op0);
    cudaGetSymbolAddress((void**)&op1, g_op1);
    cudaGetSymbolAddress((void**)&op2, g_op2);
    cudaGetSymbolAddress((void**)&op3, g_op3);
    cudaGetSymbolAddress((void**)&Se2, g_Se2);
    cudaGetSymbolAddress((void**)&So2, g_So2);
    cudaGetSymbolAddress((void**)&Ce2, g_Ce2);
    cudaGetSymbolAddress((void**)&Co2, g_Co2);
    cudaGetSymbolAddress((void**)&SoP, g_SoP);
    cudaGetSymbolAddress((void**)&CoP, g_CoP);
    cudaGetSymbolAddress((void**)&G0, g_G0); cudaGetSymbolAddress((void**)&G1, g_G1);
    cudaGetSymbolAddress((void**)&G2, g_G2); cudaGetSymbolAddress((void**)&G3, g_G3);

    cudaFuncSetAttribute(gemm_fused_kernel,
                         cudaFuncAttributeMaxDynamicSharedMemorySize, SMEM_BYTES);

    // fused prologue: inner bases (2048 blocks) + patch bases (1024) +
    // split-x (4096) in one launch
    prologue_kernel<<<7168, 256>>>(x);

    // ---- stage 1 (sin along q) ----
    FusedArgs a1;
    a1.A[0] = Se2; a1.B[0] = op0; a1.D[0] = G0;
    a1.A[1] = So2; a1.B[1] = op1; a1.D[1] = G1;
    a1.A[2] = Se2; a1.B[2] = op2; a1.D[2] = G2;
    a1.A[3] = So2; a1.B[3] = op3; a1.D[3] = G3;
    a1.PA = SoP;
    gemm_fused_kernel<<<1024 + 256, 256, SMEM_BYTES>>>(a1);
    outer_combine1_kernel<<<(2048 * 256) / 256, 256>>>();

    // ---- stage 2 (cos along p) ----
    FusedArgs a2;
    a2.A[0] = Ce2; a2.B[0] = op0; a2.D[0] = G0;
    a2.A[1] = Co2; a2.B[1] = op1; a2.D[1] = G1;
    a2.A[2] = Ce2; a2.B[2] = op2; a2.D[2] = G2;
    a2.A[3] = Co2; a2.B[3] = op3; a2.D[3] = G3;
    a2.PA = CoP;
    gemm_fused_kernel<<<1024 + 256, 256, SMEM_BYTES>>>(a2);
    outer_combine2_kernel<<<(2048 * 1024) / 256, 256>>>(out);
}